// round 3
// baseline (speedup 1.0000x reference)
#include <cuda_runtime.h>
#include <cuda_bf16.h>
#include <math.h>

#define BB 4
#define CDIM 128
#define HH 128
#define WW 128
#define NP (HH*WW)          // 16384
#define NHEADS 8
#define CH 16               // CDIM/NHEADS
#define HID 340
#define HID2 680
#define NSPLIT 32

// ---------------- scratch (device globals; no allocation allowed) ----------------
__device__ float g_xn [BB*CDIM*NP];
__device__ float g_yn [BB*CDIM*NP];
__device__ float g_q1 [BB*CDIM*NP];
__device__ float g_q  [BB*CDIM*NP];
__device__ float g_kv1[BB*2*CDIM*NP];
__device__ float g_kv [BB*2*CDIM*NP];
__device__ float g_gate[BB*64*NP];
__device__ float g_qknorm[2*BB*CDIM];
__device__ float g_attnp[NSPLIT*BB*NHEADS*CH*CH];
__device__ float g_attn [BB*NHEADS*CH*CH];
__device__ float g_av [BB*CDIM*NP];
__device__ float g_x2 [BB*CDIM*NP];
__device__ float g_z  [BB*CDIM*NP];
__device__ float g_t  [BB*HID2*NP];
__device__ float g_t2 [BB*HID2*NP];
__device__ float g_u  [BB*HID*NP];
__device__ float g_gsum;
__device__ int   g_dk;

// ---------------- init ----------------
__global__ void init_kernel() { g_gsum = 0.f; }

// ---------------- LayerNorm over channel axis (channels_first) ----------------
__global__ void __launch_bounds__(256) ln_kernel(const float* __restrict__ In,
                                                 float* __restrict__ Out,
                                                 const float* __restrict__ w,
                                                 const float* __restrict__ bta)
{
    int b = blockIdx.y;
    int pos = blockIdx.x*256 + threadIdx.x;
    const float* p = In + (size_t)b*CDIM*NP + pos;
    float s = 0.f, s2 = 0.f;
    #pragma unroll 8
    for (int c = 0; c < CDIM; c++) { float v = p[(size_t)c*NP]; s += v; s2 = fmaf(v, v, s2); }
    float mean = s * (1.f/CDIM);
    float var  = s2 * (1.f/CDIM) - mean*mean;
    float inv  = rsqrtf(var + 1e-6f);
    float* o = Out + (size_t)b*CDIM*NP + pos;
    #pragma unroll 8
    for (int c = 0; c < CDIM; c++) {
        float v = p[(size_t)c*NP];
        o[(size_t)c*NP] = w[c]*((v-mean)*inv) + bta[c];
    }
}

// ---------------- 1x1 conv = SGEMM: Out[Cout,NP] = W[Cout,Cin] * In[Cin,NP] ----------------
// Double-buffered smem pipeline; one __syncthreads per K-tile.
// mode: 0 = plain, 1 = bias+relu, 2 = +residual
#define BM 128
#define BN 128
#define BK 8
__global__ void __launch_bounds__(256) gemm1x1(const float* __restrict__ W,
                                               const float* __restrict__ In,
                                               float* __restrict__ Out,
                                               int Cout, int Cin,
                                               const float* __restrict__ bias,
                                               int mode,
                                               const float* __restrict__ resid)
{
    int b = blockIdx.z;
    const float* inb  = In  + (size_t)b*Cin*NP;
    float*       outb = Out + (size_t)b*Cout*NP;
    const float* resb = resid ? resid + (size_t)b*Cout*NP : (const float*)0;

    __shared__ float As[2][BK][BM];
    __shared__ float Bs[2][BK][BN];

    int tid = threadIdx.x;
    int tx = tid & 15, ty = tid >> 4;
    int m0 = blockIdx.y*BM, n0 = blockIdx.x*BN;

    float acc[8][8];
    #pragma unroll
    for (int i = 0; i < 8; i++)
        #pragma unroll
        for (int j = 0; j < 8; j++) acc[i][j] = 0.f;

    int am = tid >> 1;           // 0..127
    int ak = (tid & 1)*4;        // 0 or 4
    int bk = tid >> 5;           // 0..7
    int bn = (tid & 31)*4;       // 0..124

    // prologue: load tile 0 into buffer 0
    {
        #pragma unroll
        for (int j = 0; j < 4; j++) {
            int k = ak + j;
            As[0][ak+j][am] = (m0+am < Cout && k < Cin) ? W[(size_t)(m0+am)*Cin + k] : 0.f;
        }
        float4 v = make_float4(0.f,0.f,0.f,0.f);
        if (bk < Cin) v = *reinterpret_cast<const float4*>(inb + (size_t)bk*NP + n0 + bn);
        Bs[0][bk][bn+0] = v.x; Bs[0][bk][bn+1] = v.y; Bs[0][bk][bn+2] = v.z; Bs[0][bk][bn+3] = v.w;
    }
    __syncthreads();

    int cur = 0;
    for (int kt = 0; kt < Cin; kt += BK) {
        int nkt = kt + BK;
        bool has_next = (nkt < Cin);
        float a_pre[4];
        float4 b_pre = make_float4(0.f,0.f,0.f,0.f);
        if (has_next) {
            #pragma unroll
            for (int j = 0; j < 4; j++) {
                int k = nkt + ak + j;
                a_pre[j] = (m0+am < Cout && k < Cin) ? W[(size_t)(m0+am)*Cin + k] : 0.f;
            }
            int k = nkt + bk;
            if (k < Cin) b_pre = *reinterpret_cast<const float4*>(inb + (size_t)k*NP + n0 + bn);
        }

        #pragma unroll
        for (int k = 0; k < BK; k++) {
            float a[8], bb[8];
            #pragma unroll
            for (int i = 0; i < 8; i++) a[i]  = As[cur][k][ty*8+i];
            #pragma unroll
            for (int j = 0; j < 8; j++) bb[j] = Bs[cur][k][tx*8+j];
            #pragma unroll
            for (int i = 0; i < 8; i++)
                #pragma unroll
                for (int j = 0; j < 8; j++)
                    acc[i][j] = fmaf(a[i], bb[j], acc[i][j]);
        }

        if (has_next) {
            int nb = cur ^ 1;
            #pragma unroll
            for (int j = 0; j < 4; j++) As[nb][ak+j][am] = a_pre[j];
            Bs[nb][bk][bn+0] = b_pre.x; Bs[nb][bk][bn+1] = b_pre.y;
            Bs[nb][bk][bn+2] = b_pre.z; Bs[nb][bk][bn+3] = b_pre.w;
            __syncthreads();
            cur = nb;
        }
    }

    #pragma unroll
    for (int i = 0; i < 8; i++) {
        int m = m0 + ty*8 + i;
        if (m >= Cout) break;
        float bv = bias ? bias[m] : 0.f;
        float r[8];
        #pragma unroll
        for (int j = 0; j < 8; j++) {
            float v = acc[i][j] + bv;
            if (mode == 1) v = fmaxf(v, 0.f);
            r[j] = v;
        }
        size_t off = (size_t)m*NP + n0 + tx*8;
        if (mode == 2) {
            float4 r0 = *reinterpret_cast<const float4*>(resb + off);
            float4 r1 = *reinterpret_cast<const float4*>(resb + off + 4);
            r[0]+=r0.x; r[1]+=r0.y; r[2]+=r0.z; r[3]+=r0.w;
            r[4]+=r1.x; r[5]+=r1.y; r[6]+=r1.z; r[7]+=r1.w;
        }
        *reinterpret_cast<float4*>(outb + off)     = make_float4(r[0],r[1],r[2],r[3]);
        *reinterpret_cast<float4*>(outb + off + 4) = make_float4(r[4],r[5],r[6],r[7]);
    }
}

// ---------------- depthwise 3x3 conv, pad=1 (plain) ----------------
__global__ void __launch_bounds__(256) dwconv3(const float* __restrict__ In, int inCtot, int inCbase,
                                               const float* __restrict__ Wd,
                                               float* __restrict__ Out, int outCtot,
                                               int C)
{
    int bc = blockIdx.z;
    int b = bc / C, c = bc % C;
    const float* plane  = In  + ((size_t)b*inCtot + inCbase + c)*NP;
    float*       oplane = Out + ((size_t)b*outCtot + c)*NP;

    __shared__ float t[10][34];
    int tid = threadIdx.x;
    int x0 = blockIdx.x*32, y0 = blockIdx.y*8;
    for (int i = tid; i < 340; i += 256) {
        int sy = i / 34, sx = i % 34;
        int gy = y0 + sy - 1, gx = x0 + sx - 1;
        t[sy][sx] = (gy >= 0 && gy < HH && gx >= 0 && gx < WW) ? plane[gy*WW + gx] : 0.f;
    }
    __syncthreads();
    int tx = tid & 31, ty = tid >> 5;
    const float* w = Wd + (size_t)c*9;
    float s = 0.f;
    #pragma unroll
    for (int ky = 0; ky < 3; ky++)
        #pragma unroll
        for (int kx = 0; kx < 3; kx++)
            s = fmaf(w[ky*3+kx], t[ty+ky][tx+kx], s);
    oplane[(y0+ty)*WW + x0 + tx] = s;
}

// ---------------- fused IEL tail: u = (tanh(dw1(x1))+x1) * (tanh(dw2(x2))+x2) ----------------
__global__ void __launch_bounds__(256) dw12_fused(const float* __restrict__ T2,
                                                  const float* __restrict__ W1,
                                                  const float* __restrict__ W2,
                                                  float* __restrict__ U)
{
    int bc = blockIdx.z;
    int b = bc / HID, c = bc % HID;
    const float* p1 = T2 + ((size_t)b*HID2 + c)*NP;
    const float* p2 = T2 + ((size_t)b*HID2 + HID + c)*NP;
    float*       ou = U  + ((size_t)b*HID + c)*NP;

    __shared__ float t1[10][34];
    __shared__ float t2s[10][34];
    int tid = threadIdx.x;
    int x0 = blockIdx.x*32, y0 = blockIdx.y*8;
    for (int i = tid; i < 340; i += 256) {
        int sy = i / 34, sx = i % 34;
        int gy = y0 + sy - 1, gx = x0 + sx - 1;
        bool ok = (gy >= 0 && gy < HH && gx >= 0 && gx < WW);
        int gidx = gy*WW + gx;
        t1[sy][sx]  = ok ? p1[gidx] : 0.f;
        t2s[sy][sx] = ok ? p2[gidx] : 0.f;
    }
    __syncthreads();
    int tx = tid & 31, ty = tid >> 5;
    const float* w1 = W1 + (size_t)c*9;
    const float* w2 = W2 + (size_t)c*9;
    float s1 = 0.f, s2 = 0.f;
    #pragma unroll
    for (int ky = 0; ky < 3; ky++)
        #pragma unroll
        for (int kx = 0; kx < 3; kx++) {
            s1 = fmaf(w1[ky*3+kx], t1[ty+ky][tx+kx],  s1);
            s2 = fmaf(w2[ky*3+kx], t2s[ty+ky][tx+kx], s2);
        }
    float r1 = tanhf(s1) + t1[ty+1][tx+1];
    float r2 = tanhf(s2) + t2s[ty+1][tx+1];
    ou[(y0+ty)*WW + x0 + tx] = r1 * r2;
}

// ---------------- gate tail: g2 1x1 (64->1) + sigmoid + global sum ----------------
__global__ void __launch_bounds__(256) gate2_kernel(const float* __restrict__ w2,
                                                    const float* __restrict__ b2)
{
    int b = blockIdx.y;
    int pos = blockIdx.x*256 + threadIdx.x;
    const float* p = g_gate + (size_t)b*64*NP + pos;
    float s = b2[0];
    #pragma unroll
    for (int c = 0; c < 64; c++) s = fmaf(w2[c], p[(size_t)c*NP], s);
    float sig = 1.f/(1.f + expf(-s));
    __shared__ float red[256];
    red[threadIdx.x] = sig;
    __syncthreads();
    for (int off = 128; off > 0; off >>= 1) {
        if (threadIdx.x < off) red[threadIdx.x] += red[threadIdx.x+off];
        __syncthreads();
    }
    if (threadIdx.x == 0) atomicAdd(&g_gsum, red[0]);
}

__global__ void dk_kernel() {
    float mean = g_gsum / (float)(BB*NP);
    int dk = (int)(16.f * mean);   // trunc, matches astype(int32)
    if (dk < 1) dk = 1;
    if (dk > CH) dk = CH;
    g_dk = dk;
}

// ---------------- row L2 norms of q (first 512 rows) and k (next 512) ----------------
__global__ void __launch_bounds__(256) norm_kernel() {
    int r = blockIdx.x;
    const float* p;
    if (r < BB*CDIM) {
        p = g_q + (size_t)r*NP;
    } else {
        int r2 = r - BB*CDIM;
        int b = r2 >> 7, c = r2 & 127;
        p = g_kv + ((size_t)b*2*CDIM + c)*NP;
    }
    float s = 0.f;
    for (int i = threadIdx.x; i < NP; i += 256) { float v = p[i]; s = fmaf(v, v, s); }
    __shared__ float red[256];
    red[threadIdx.x] = s;
    __syncthreads();
    for (int off = 128; off > 0; off >>= 1) {
        if (threadIdx.x < off) red[threadIdx.x] += red[threadIdx.x+off];
        __syncthreads();
    }
    if (threadIdx.x == 0) g_qknorm[r] = sqrtf(red[0]);
}

// ---------------- attention logits: partial dots over N splits ----------------
__global__ void __launch_bounds__(256) attn_partial() {
    int split = blockIdx.x;
    int bh = blockIdx.y;
    int b = bh >> 3, h = bh & 7;
    int tid = threadIdx.x;
    int c = tid >> 4, d = tid & 15;
    __shared__ float qs[128*17];
    __shared__ float ks[128*17];
    float acc = 0.f;
    for (int sub = 0; sub < 4; sub++) {
        int n0 = split*512 + sub*128;
        __syncthreads();
        for (int i = tid; i < 2048; i += 256) {
            int cc = i >> 7, n = i & 127;
            qs[n*17+cc] = g_q [((size_t)b*CDIM   + h*CH + cc)*NP + n0 + n];
            ks[n*17+cc] = g_kv[((size_t)b*2*CDIM + h*CH + cc)*NP + n0 + n];
        }
        __syncthreads();
        #pragma unroll 8
        for (int n = 0; n < 128; n++)
            acc = fmaf(qs[n*17+c], ks[n*17+d], acc);
    }
    g_attnp[((size_t)split*BB*NHEADS + bh)*256 + tid] = acc;
}

__global__ void __launch_bounds__(256) attn_reduce(const float* __restrict__ temp) {
    int bh = blockIdx.x;
    int b = bh >> 3, h = bh & 7;
    int tid = threadIdx.x;
    int c = tid >> 4, d = tid & 15;
    float s = 0.f;
    for (int sp = 0; sp < NSPLIT; sp++)
        s += g_attnp[((size_t)sp*BB*NHEADS + bh)*256 + tid];
    float qn = fmaxf(g_qknorm[b*CDIM + h*CH + c], 1e-12f);
    float kn = fmaxf(g_qknorm[BB*CDIM + b*CDIM + h*CH + d], 1e-12f);
    g_attn[(size_t)bh*256 + tid] = s * temp[h] / (qn * kn);
}

// ---------------- exact rank-based top-k mask + softmax ----------------
__global__ void masksoftmax() {
    int row = blockIdx.x*blockDim.x + threadIdx.x;
    if (row >= BB*NHEADS*CH) return;
    float* base = g_attn + (size_t)row*16;
    float v[16];
    #pragma unroll
    for (int j = 0; j < 16; j++) v[j] = base[j];
    int dk = g_dk;
    bool keep[16];
    float m = -1e30f;
    #pragma unroll
    for (int j = 0; j < 16; j++) {
        int rank = 0;
        #pragma unroll
        for (int i = 0; i < 16; i++)
            rank += (v[i] > v[j]) || (v[i] == v[j] && i < j);
        keep[j] = rank < dk;
        if (keep[j] && v[j] > m) m = v[j];
    }
    float e[16];
    float s = 0.f;
    #pragma unroll
    for (int j = 0; j < 16; j++) { e[j] = keep[j] ? expf(v[j]-m) : 0.f; s += e[j]; }
    float inv = 1.f/s;
    #pragma unroll
    for (int j = 0; j < 16; j++) base[j] = e[j]*inv;
}

// ---------------- out = attn @ v ----------------
__global__ void __launch_bounds__(256) av_kernel() {
    int bh = blockIdx.y;
    int b = bh >> 3, h = bh & 7;
    int n = blockIdx.x*256 + threadIdx.x;
    __shared__ float a[256];
    a[threadIdx.x] = g_attn[(size_t)bh*256 + threadIdx.x];
    __syncthreads();
    float acc[16];
    #pragma unroll
    for (int c = 0; c < 16; c++) acc[c] = 0.f;
    #pragma unroll
    for (int d = 0; d < 16; d++) {
        float vv = g_kv[((size_t)b*2*CDIM + CDIM + h*CH + d)*NP + n];
        #pragma unroll
        for (int c = 0; c < 16; c++) acc[c] = fmaf(a[c*16+d], vv, acc[c]);
    }
    #pragma unroll
    for (int c = 0; c < 16; c++)
        g_av[((size_t)b*CDIM + h*CH + c)*NP + n] = acc[c];
}

// ---------------- host launcher ----------------
extern "C" void kernel_launch(void* const* d_in, const int* in_sizes, int n_in,
                              void* d_out, int out_size)
{
    const float* x      = (const float*)d_in[0];
    const float* y      = (const float*)d_in[1];
    const float* ln_w   = (const float*)d_in[2];
    const float* ln_b   = (const float*)d_in[3];
    const float* temp   = (const float*)d_in[4];
    const float* q_w    = (const float*)d_in[5];
    const float* qdw_w  = (const float*)d_in[6];
    const float* kv_w   = (const float*)d_in[7];
    const float* kvdw_w = (const float*)d_in[8];
    const float* po_w   = (const float*)d_in[9];
    const float* g1_w   = (const float*)d_in[10];
    const float* g1_b   = (const float*)d_in[11];
    const float* g2_w   = (const float*)d_in[12];
    const float* g2_b   = (const float*)d_in[13];
    const float* pin_w  = (const float*)d_in[14];
    const float* dw_w   = (const float*)d_in[15];
    const float* dw1_w  = (const float*)d_in[16];
    const float* dw2_w  = (const float*)d_in[17];
    const float* pout_w = (const float*)d_in[18];
    float* out = (float*)d_out;

    float *p_xn, *p_yn, *p_q1, *p_q, *p_kv1, *p_kv, *p_gate, *p_av, *p_x2, *p_z, *p_t, *p_t2, *p_u;
    cudaGetSymbolAddress((void**)&p_xn,  g_xn);
    cudaGetSymbolAddress((void**)&p_yn,  g_yn);
    cudaGetSymbolAddress((void**)&p_q1,  g_q1);
    cudaGetSymbolAddress((void**)&p_q,   g_q);
    cudaGetSymbolAddress((void**)&p_kv1, g_kv1);
    cudaGetSymbolAddress((void**)&p_kv,  g_kv);
    cudaGetSymbolAddress((void**)&p_gate,g_gate);
    cudaGetSymbolAddress((void**)&p_av,  g_av);
    cudaGetSymbolAddress((void**)&p_x2,  g_x2);
    cudaGetSymbolAddress((void**)&p_z,   g_z);
    cudaGetSymbolAddress((void**)&p_t,   g_t);
    cudaGetSymbolAddress((void**)&p_t2,  g_t2);
    cudaGetSymbolAddress((void**)&p_u,   g_u);

    dim3 lnGrid(NP/256, BB);

    init_kernel<<<1,1>>>();

    // LayerNorms of x and y
    ln_kernel<<<lnGrid, 256>>>(x, p_xn, ln_w, ln_b);
    ln_kernel<<<lnGrid, 256>>>(y, p_yn, ln_w, ln_b);

    // q / kv / gate1 projections
    gemm1x1<<<dim3(NP/BN, 1, BB), 256>>>(q_w,  p_xn, p_q1,  CDIM,   CDIM, (const float*)0, 0, (const float*)0);
    gemm1x1<<<dim3(NP/BN, 2, BB), 256>>>(kv_w, p_yn, p_kv1, 2*CDIM, CDIM, (const float*)0, 0, (const float*)0);
    gemm1x1<<<dim3(NP/BN, 1, BB), 256>>>(g1_w, p_xn, p_gate, 64,    CDIM, g1_b,            1, (const float*)0);

    // depthwise convs for q / kv
    dwconv3<<<dim3(WW/32, HH/8, BB*CDIM),   256>>>(p_q1,  CDIM,   0, qdw_w,  p_q,  CDIM,   CDIM);
    dwconv3<<<dim3(WW/32, HH/8, BB*2*CDIM), 256>>>(p_kv1, 2*CDIM, 0, kvdw_w, p_kv, 2*CDIM, 2*CDIM);

    // gate tail -> dk
    gate2_kernel<<<dim3(NP/256, BB), 256>>>(g2_w, g2_b);
    dk_kernel<<<1,1>>>();

    // norms, attention logits, mask+softmax, attn@v
    norm_kernel<<<2*BB*CDIM, 256>>>();
    attn_partial<<<dim3(NSPLIT, BB*NHEADS), 256>>>();
    attn_reduce<<<BB*NHEADS, 256>>>(temp);
    masksoftmax<<<2, 256>>>();
    av_kernel<<<dim3(NP/256, BB*NHEADS), 256>>>();

    // project_out + residual
    gemm1x1<<<dim3(NP/BN, 1, BB), 256>>>(po_w, p_av, p_x2, CDIM, CDIM, (const float*)0, 2, x);

    // IEL
    ln_kernel<<<lnGrid, 256>>>(p_x2, p_z, ln_w, ln_b);
    gemm1x1<<<dim3(NP/BN, (HID2+BM-1)/BM, BB), 256>>>(pin_w, p_z, p_t, HID2, CDIM, (const float*)0, 0, (const float*)0);
    dwconv3<<<dim3(WW/32, HH/8, BB*HID2), 256>>>(p_t, HID2, 0, dw_w, p_t2, HID2, HID2);
    // fused: u = (tanh(dw1(x1))+x1) * (tanh(dw2(x2))+x2)
    dw12_fused<<<dim3(WW/32, HH/8, BB*HID), 256>>>(p_t2, dw1_w, dw2_w, p_u);
    // pout + residual -> d_out
    gemm1x1<<<dim3(NP/BN, 1, BB), 256>>>(pout_w, p_u, out, CDIM, HID, (const float*)0, 2, p_x2);
}

// round 7
// speedup vs baseline: 1.1719x; 1.1719x over previous
#include <cuda_runtime.h>
#include <cuda_bf16.h>
#include <mma.h>
#include <math.h>

using namespace nvcuda;

#define BB 4
#define CDIM 128
#define HH 128
#define WW 128
#define NP (HH*WW)          // 16384
#define NHEADS 8
#define CH 16
#define HID 340
#define HID2 680
#define TPAD 688            // padded row stride for pin output
#define NSPLIT 32

typedef __nv_bfloat16 bf16;
typedef unsigned int u32;

// ---------------- scratch (device globals; no allocation allowed) ----------------
// NOTE: explicit 256B alignment — uint4 vector loads require 16B-aligned bases.
__device__ __align__(256) bf16 g_xnh[BB*CDIM*NP], g_xnl[BB*CDIM*NP];
__device__ __align__(256) bf16 g_ynh[BB*CDIM*NP], g_ynl[BB*CDIM*NP];
__device__ __align__(256) bf16 g_zh [BB*CDIM*NP], g_zl [BB*CDIM*NP];
__device__ __align__(256) bf16 g_avh[BB*CDIM*NP], g_avl[BB*CDIM*NP];
__device__ __align__(256) bf16 g_uh [BB*HID*NP],  g_ul [BB*HID*NP];
// bf16 hi/lo weights, K-padded row-major [Cout, Kw]
__device__ __align__(256) bf16 g_wqh [128*128],  g_wql [128*128];
__device__ __align__(256) bf16 g_wkvh[256*128],  g_wkvl[256*128];
__device__ __align__(256) bf16 g_wpoh[128*128],  g_wpol[128*128];
__device__ __align__(256) bf16 g_wg1h[64*128],   g_wg1l[64*128];
__device__ __align__(256) bf16 g_wpih[680*128],  g_wpil[680*128];
__device__ __align__(256) bf16 g_wpth[128*384],  g_wptl[128*384];
// fp32 scratch
__device__ float g_q1 [BB*CDIM*NP];
__device__ float g_q  [BB*CDIM*NP];
__device__ float g_kv1[BB*2*CDIM*NP];
__device__ float g_kv [BB*2*CDIM*NP];
__device__ float g_gate[BB*128*NP];          // padded 64 -> 128 rows per batch
__device__ float g_qknorm[2*BB*CDIM];
__device__ float g_attnp[NSPLIT*BB*NHEADS*CH*CH];
__device__ float g_attn [BB*NHEADS*CH*CH];
__device__ float g_x2 [BB*CDIM*NP];
__device__ float g_t  [BB*TPAD*NP];          // padded 680 -> 688 rows per batch
__device__ float g_t2 [BB*HID2*NP];
__device__ float g_gsum;
__device__ int   g_dk;

// ---------------- helpers ----------------
__device__ __forceinline__ void f32split(float v, bf16& h, bf16& l) {
    h = __float2bfloat16(v);
    l = __float2bfloat16(v - __bfloat162float(h));
}

__global__ void init_kernel() { g_gsum = 0.f; }

__global__ void convert_w(const float* __restrict__ W, bf16* __restrict__ hi, bf16* __restrict__ lo,
                          int Cout, int Cin, int Kw)
{
    int idx = blockIdx.x*256 + threadIdx.x;
    if (idx >= Cout*Kw) return;
    int r = idx / Kw, k = idx - r*Kw;
    float v = (k < Cin) ? W[(size_t)r*Cin + k] : 0.f;
    bf16 h, l; f32split(v, h, l);
    hi[idx] = h; lo[idx] = l;
}

// ---------------- LayerNorm (channel axis) -> bf16 hi/lo ----------------
__global__ void __launch_bounds__(256) ln_kernel(const float* __restrict__ In,
                                                 bf16* __restrict__ Oh, bf16* __restrict__ Ol,
                                                 const float* __restrict__ w,
                                                 const float* __restrict__ bta)
{
    int b = blockIdx.y;
    int pos = blockIdx.x*256 + threadIdx.x;
    const float* p = In + (size_t)b*CDIM*NP + pos;
    float s = 0.f, s2 = 0.f;
    #pragma unroll 8
    for (int c = 0; c < CDIM; c++) { float v = p[(size_t)c*NP]; s += v; s2 = fmaf(v, v, s2); }
    float mean = s * (1.f/CDIM);
    float var  = s2 * (1.f/CDIM) - mean*mean;
    float inv  = rsqrtf(var + 1e-6f);
    #pragma unroll 8
    for (int c = 0; c < CDIM; c++) {
        float v = p[(size_t)c*NP];
        float o = w[c]*((v-mean)*inv) + bta[c];
        bf16 h, l; f32split(o, h, l);
        Oh[((size_t)b*CDIM+c)*NP + pos] = h;
        Ol[((size_t)b*CDIM+c)*NP + pos] = l;
    }
}

// ---------------- wmma split-bf16 GEMM: Out[Cout,NP] = W[Cout,Cin] * In[Cin,NP] ----------------
// 8 warps (4 rows x 2 cols), block tile 128x128, warp tile 32x64, BK=32.
// 3 MMAs per tile-k: hi*hi + hi*lo + lo*hi. mode: 0 plain, 1 bias+relu, 2 +residual.
#define ALD 48
#define BLD 136

__global__ void __launch_bounds__(256, 1)
gemm_wmma(const bf16* __restrict__ Whi, const bf16* __restrict__ Wlo, int Kw,
          const bf16* __restrict__ Ihi, const bf16* __restrict__ Ilo, int Cin,
          float* __restrict__ Out, int CoutW, int CoutPad,
          const float* __restrict__ bias, int mode, const float* __restrict__ resid)
{
    __shared__ __align__(16) bf16 sAh[128*ALD], sAl[128*ALD];
    __shared__ __align__(16) bf16 sBh[32*BLD],  sBl[32*BLD];

    const int tid = threadIdx.x;
    const int warp = tid >> 5, lane = tid & 31;
    const int wr = warp >> 1, wc = warp & 1;
    const int bb = blockIdx.z;
    const int n0 = blockIdx.x * 128;
    const int m0 = blockIdx.y * 128;

    const bf16* inh = Ihi + (size_t)bb*Cin*NP;
    const bf16* inl = Ilo + (size_t)bb*Cin*NP;

    const int a_row0 = (tid*2) >> 2,   a_c0 = ((tid*2) & 3) * 8;
    const int a_row1 = (tid*2+1) >> 2, a_c1 = ((tid*2+1) & 3) * 8;
    const int b_row0 = (tid*2) >> 4,   b_c0 = ((tid*2) & 15) * 8;
    const int b_row1 = (tid*2+1) >> 4, b_c1 = ((tid*2+1) & 15) * 8;

    uint4 pa_h[2], pa_l[2], pb_h[2], pb_l[2];
    const uint4 z4 = make_uint4(0,0,0,0);

    auto ldg = [&](int kc0) {
        int rg0 = m0 + a_row0, rg1 = m0 + a_row1;
        pa_h[0] = (rg0 < CoutW) ? *(const uint4*)(Whi + (size_t)rg0*Kw + kc0 + a_c0) : z4;
        pa_l[0] = (rg0 < CoutW) ? *(const uint4*)(Wlo + (size_t)rg0*Kw + kc0 + a_c0) : z4;
        pa_h[1] = (rg1 < CoutW) ? *(const uint4*)(Whi + (size_t)rg1*Kw + kc0 + a_c1) : z4;
        pa_l[1] = (rg1 < CoutW) ? *(const uint4*)(Wlo + (size_t)rg1*Kw + kc0 + a_c1) : z4;
        int k0 = kc0 + b_row0, k1 = kc0 + b_row1;
        pb_h[0] = (k0 < Cin) ? *(const uint4*)(inh + (size_t)k0*NP + n0 + b_c0) : z4;
        pb_l[0] = (k0 < Cin) ? *(const uint4*)(inl + (size_t)k0*NP + n0 + b_c0) : z4;
        pb_h[1] = (k1 < Cin) ? *(const uint4*)(inh + (size_t)k1*NP + n0 + b_c1) : z4;
        pb_l[1] = (k1 < Cin) ? *(const uint4*)(inl + (size_t)k1*NP + n0 + b_c1) : z4;
    };
    auto sts = [&]() {
        *(uint4*)&sAh[a_row0*ALD + a_c0] = pa_h[0];
        *(uint4*)&sAl[a_row0*ALD + a_c0] = pa_l[0];
        *(uint4*)&sAh[a_row1*ALD + a_c1] = pa_h[1];
        *(uint4*)&sAl[a_row1*ALD + a_c1] = pa_l[1];
        *(uint4*)&sBh[b_row0*BLD + b_c0] = pb_h[0];
        *(uint4*)&sBl[b_row0*BLD + b_c0] = pb_l[0];
        *(uint4*)&sBh[b_row1*BLD + b_c1] = pb_h[1];
        *(uint4*)&sBl[b_row1*BLD + b_c1] = pb_l[1];
    };

    wmma::fragment<wmma::accumulator, 16,16,16, float> acc[2][4];
    #pragma unroll
    for (int mt = 0; mt < 2; mt++)
        #pragma unroll
        for (int nt = 0; nt < 4; nt++) wmma::fill_fragment(acc[mt][nt], 0.f);

    int nchunks = (Cin + 31) >> 5;
    ldg(0);
    sts();

    for (int chn = 0; chn < nchunks; chn++) {
        __syncthreads();
        bool nxt = (chn + 1) < nchunks;
        if (nxt) ldg((chn+1) << 5);

        wmma::fragment<wmma::matrix_a, 16,16,16, bf16, wmma::row_major> fah[2], fal[2];
        wmma::fragment<wmma::matrix_b, 16,16,16, bf16, wmma::row_major> fbh[4], fbl[4];
        #pragma unroll
        for (int ks = 0; ks < 2; ks++) {
            int k16 = ks * 16;
            #pragma unroll
            for (int mt = 0; mt < 2; mt++) {
                wmma::load_matrix_sync(fah[mt], &sAh[(wr*32 + mt*16)*ALD + k16], ALD);
                wmma::load_matrix_sync(fal[mt], &sAl[(wr*32 + mt*16)*ALD + k16], ALD);
            }
            #pragma unroll
            for (int nt = 0; nt < 4; nt++) {
                wmma::load_matrix_sync(fbh[nt], &sBh[k16*BLD + wc*64 + nt*16], BLD);
                wmma::load_matrix_sync(fbl[nt], &sBl[k16*BLD + wc*64 + nt*16], BLD);
            }
            #pragma unroll
            for (int mt = 0; mt < 2; mt++)
                #pragma unroll
                for (int nt = 0; nt < 4; nt++) {
                    wmma::mma_sync(acc[mt][nt], fah[mt], fbh[nt], acc[mt][nt]);
                    wmma::mma_sync(acc[mt][nt], fah[mt], fbl[nt], acc[mt][nt]);
                    wmma::mma_sync(acc[mt][nt], fal[mt], fbh[nt], acc[mt][nt]);
                }
        }
        __syncthreads();
        if (nxt) sts();
    }

    // epilogue: stage each 16x16 tile through smem, apply op, vector store
    __syncthreads();
    float* stage = reinterpret_cast<float*>(sAh) + warp * 256;
    const int erow = lane >> 1, ec0 = (lane & 1) * 8;
    #pragma unroll
    for (int mt = 0; mt < 2; mt++) {
        #pragma unroll
        for (int nt = 0; nt < 4; nt++) {
            wmma::store_matrix_sync(stage, acc[mt][nt], 16, wmma::mem_row_major);
            __syncwarp();
            int m = m0 + wr*32 + mt*16 + erow;
            int n = n0 + wc*64 + nt*16 + ec0;
            if (m < CoutPad) {
                float v[8];
                #pragma unroll
                for (int j = 0; j < 8; j++) v[j] = stage[erow*16 + ec0 + j];
                if (mode == 1) {
                    float bv = (m < CoutW) ? bias[m] : 0.f;
                    #pragma unroll
                    for (int j = 0; j < 8; j++) v[j] = fmaxf(v[j] + bv, 0.f);
                } else if (mode == 2) {
                    const float* rp = resid + ((size_t)bb*CoutPad + m)*NP + n;
                    float4 r0 = *(const float4*)rp;
                    float4 r1 = *(const float4*)(rp + 4);
                    v[0]+=r0.x; v[1]+=r0.y; v[2]+=r0.z; v[3]+=r0.w;
                    v[4]+=r1.x; v[5]+=r1.y; v[6]+=r1.z; v[7]+=r1.w;
                }
                float* op = Out + ((size_t)bb*CoutPad + m)*NP + n;
                *(float4*)op       = make_float4(v[0],v[1],v[2],v[3]);
                *(float4*)(op + 4) = make_float4(v[4],v[5],v[6],v[7]);
            }
            __syncwarp();
        }
    }
}

// ---------------- depthwise 3x3 conv, pad=1 (fp32) ----------------
__global__ void __launch_bounds__(256) dwconv3(const float* __restrict__ In, int inCtot, int inCbase,
                                               const float* __restrict__ Wd,
                                               float* __restrict__ Out, int outCtot,
                                               int C)
{
    int bc = blockIdx.z;
    int b = bc / C, c = bc % C;
    const float* plane  = In  + ((size_t)b*inCtot + inCbase + c)*NP;
    float*       oplane = Out + ((size_t)b*outCtot + c)*NP;

    __shared__ float t[10][34];
    int tid = threadIdx.x;
    int x0 = blockIdx.x*32, y0 = blockIdx.y*8;
    for (int i = tid; i < 340; i += 256) {
        int sy = i / 34, sx = i % 34;
        int gy = y0 + sy - 1, gx = x0 + sx - 1;
        t[sy][sx] = (gy >= 0 && gy < HH && gx >= 0 && gx < WW) ? plane[gy*WW + gx] : 0.f;
    }
    __syncthreads();
    int tx = tid & 31, ty = tid >> 5;
    const float* w = Wd + (size_t)c*9;
    float s = 0.f;
    #pragma unroll
    for (int ky = 0; ky < 3; ky++)
        #pragma unroll
        for (int kx = 0; kx < 3; kx++)
            s = fmaf(w[ky*3+kx], t[ty+ky][tx+kx], s);
    oplane[(y0+ty)*WW + x0 + tx] = s;
}

// ---------------- fused IEL tail -> u hi/lo ----------------
__global__ void __launch_bounds__(256) dw12_fused(const float* __restrict__ T2,
                                                  const float* __restrict__ W1,
                                                  const float* __restrict__ W2)
{
    int bc = blockIdx.z;
    int b = bc / HID, c = bc % HID;
    const float* p1 = T2 + ((size_t)b*HID2 + c)*NP;
    const float* p2 = T2 + ((size_t)b*HID2 + HID + c)*NP;
    size_t uoff = ((size_t)b*HID + c)*NP;

    __shared__ float t1[10][34];
    __shared__ float t2s[10][34];
    int tid = threadIdx.x;
    int x0 = blockIdx.x*32, y0 = blockIdx.y*8;
    for (int i = tid; i < 340; i += 256) {
        int sy = i / 34, sx = i % 34;
        int gy = y0 + sy - 1, gx = x0 + sx - 1;
        bool ok = (gy >= 0 && gy < HH && gx >= 0 && gx < WW);
        int gidx = gy*WW + gx;
        t1[sy][sx]  = ok ? p1[gidx] : 0.f;
        t2s[sy][sx] = ok ? p2[gidx] : 0.f;
    }
    __syncthreads();
    int tx = tid & 31, ty = tid >> 5;
    const float* w1 = W1 + (size_t)c*9;
    const float* w2 = W2 + (size_t)c*9;
    float s1 = 0.f, s2 = 0.f;
    #pragma unroll
    for (int ky = 0; ky < 3; ky++)
        #pragma unroll
        for (int kx = 0; kx < 3; kx++) {
            s1 = fmaf(w1[ky*3+kx], t1[ty+ky][tx+kx],  s1);
            s2 = fmaf(w2[ky*3+kx], t2s[ty+ky][tx+kx], s2);
        }
    float r1 = tanhf(s1) + t1[ty+1][tx+1];
    float r2 = tanhf(s2) + t2s[ty+1][tx+1];
    float u = r1 * r2;
    bf16 h, l; f32split(u, h, l);
    int idx = (y0+ty)*WW + x0 + tx;
    g_uh[uoff + idx] = h;
    g_ul[uoff + idx] = l;
}

// ---------------- gate tail ----------------
__global__ void __launch_bounds__(256) gate2_kernel(const float* __restrict__ w2,
                                                    const float* __restrict__ b2)
{
    int b = blockIdx.y;
    int pos = blockIdx.x*256 + threadIdx.x;
    const float* p = g_gate + (size_t)b*128*NP + pos;   // padded stride
    float s = b2[0];
    #pragma unroll
    for (int c = 0; c < 64; c++) s = fmaf(w2[c], p[(size_t)c*NP], s);
    float sig = 1.f/(1.f + expf(-s));
    __shared__ float red[256];
    red[threadIdx.x] = sig;
    __syncthreads();
    for (int off = 128; off > 0; off >>= 1) {
        if (threadIdx.x < off) red[threadIdx.x] += red[threadIdx.x+off];
        __syncthreads();
    }
    if (threadIdx.x == 0) atomicAdd(&g_gsum, red[0]);
}

__global__ void dk_kernel() {
    float mean = g_gsum / (float)(BB*NP);
    int dk = (int)(16.f * mean);
    if (dk < 1) dk = 1;
    if (dk > CH) dk = CH;
    g_dk = dk;
}

// ---------------- row L2 norms ----------------
__global__ void __launch_bounds__(256) norm_kernel() {
    int r = blockIdx.x;
    const float* p;
    if (r < BB*CDIM) {
        p = g_q + (size_t)r*NP;
    } else {
        int r2 = r - BB*CDIM;
        int b = r2 >> 7, c = r2 & 127;
        p = g_kv + ((size_t)b*2*CDIM + c)*NP;
    }
    float s = 0.f;
    for (int i = threadIdx.x; i < NP; i += 256) { float v = p[i]; s = fmaf(v, v, s); }
    __shared__ float red[256];
    red[threadIdx.x] = s;
    __syncthreads();
    for (int off = 128; off > 0; off >>= 1) {
        if (threadIdx.x < off) red[threadIdx.x] += red[threadIdx.x+off];
        __syncthreads();
    }
    if (threadIdx.x == 0) g_qknorm[r] = sqrtf(red[0]);
}

// ---------------- attention logits ----------------
__global__ void __launch_bounds__(256) attn_partial() {
    int split = blockIdx.x;
    int bh = blockIdx.y;
    int b = bh >> 3, h = bh & 7;
    int tid = threadIdx.x;
    int c = tid >> 4, d = tid & 15;
    __shared__ float qs[128*17];
    __shared__ float ks[128*17];
    float acc = 0.f;
    for (int sub = 0; sub < 4; sub++) {
        int n0 = split*512 + sub*128;
        __syncthreads();
        for (int i = tid; i < 2048; i += 256) {
            int cc = i >> 7, n = i & 127;
            qs[n*17+cc] = g_q [((size_t)b*CDIM   + h*CH + cc)*NP + n0 + n];
            ks[n*17+cc] = g_kv[((size_t)b*2*CDIM + h*CH + cc)*NP + n0 + n];
        }
        __syncthreads();
        #pragma unroll 8
        for (int n = 0; n < 128; n++)
            acc = fmaf(qs[n*17+c], ks[n*17+d], acc);
    }
    g_attnp[((size_t)split*BB*NHEADS + bh)*256 + tid] = acc;
}

__global__ void __launch_bounds__(256) attn_reduce(const float* __restrict__ temp) {
    int bh = blockIdx.x;
    int b = bh >> 3, h = bh & 7;
    int tid = threadIdx.x;
    int c = tid >> 4, d = tid & 15;
    float s = 0.f;
    for (int sp = 0; sp < NSPLIT; sp++)
        s += g_attnp[((size_t)sp*BB*NHEADS + bh)*256 + tid];
    float qn = fmaxf(g_qknorm[b*CDIM + h*CH + c], 1e-12f);
    float kn = fmaxf(g_qknorm[BB*CDIM + b*CDIM + h*CH + d], 1e-12f);
    g_attn[(size_t)bh*256 + tid] = s * temp[h] / (qn * kn);
}

// ---------------- top-k mask + softmax ----------------
__global__ void masksoftmax() {
    int row = blockIdx.x*blockDim.x + threadIdx.x;
    if (row >= BB*NHEADS*CH) return;
    float* base = g_attn + (size_t)row*16;
    float v[16];
    #pragma unroll
    for (int j = 0; j < 16; j++) v[j] = base[j];
    int dk = g_dk;
    bool keep[16];
    float m = -1e30f;
    #pragma unroll
    for (int j = 0; j < 16; j++) {
        int rank = 0;
        #pragma unroll
        for (int i = 0; i < 16; i++)
            rank += (v[i] > v[j]) || (v[i] == v[j] && i < j);
        keep[j] = rank < dk;
        if (keep[j] && v[j] > m) m = v[j];
    }
    float e[16];
    float s = 0.f;
    #pragma unroll
    for (int j = 0; j < 16; j++) { e[j] = keep[j] ? expf(v[j]-m) : 0.f; s += e[j]; }
    float inv = 1.f/s;
    #pragma unroll
    for (int j = 0; j < 16; j++) base[j] = e[j]*inv;
}

// ---------------- out = attn @ v -> av hi/lo ----------------
__global__ void __launch_bounds__(256) av_kernel() {
    int bh = blockIdx.y;
    int b = bh >> 3, h = bh & 7;
    int n = blockIdx.x*256 + threadIdx.x;
    __shared__ float a[256];
    a[threadIdx.x] = g_attn[(size_t)bh*256 + threadIdx.x];
    __syncthreads();
    float acc[16];
    #pragma unroll
    for (int c = 0; c < 16; c++) acc[c] = 0.f;
    #pragma unroll
    for (int d = 0; d < 16; d++) {
        float vv = g_kv[((size_t)b*2*CDIM + CDIM + h*CH + d)*NP + n];
        #pragma unroll
        for (int c = 0; c < 16; c++) acc[c] = fmaf(a[c*16+d], vv, acc[c]);
    }
    #pragma unroll
    for (int c = 0; c < 16; c++) {
        bf16 hh, ll; f32split(acc[c], hh, ll);
        g_avh[((size_t)b*CDIM + h*CH + c)*NP + n] = hh;
        g_avl[((size_t)b*CDIM + h*CH + c)*NP + n] = ll;
    }
}

// ---------------- host launcher ----------------
extern "C" void kernel_launch(void* const* d_in, const int* in_sizes, int n_in,
                              void* d_out, int out_size)
{
    const float* x      = (const float*)d_in[0];
    const float* y      = (const float*)d_in[1];
    const float* ln_w   = (const float*)d_in[2];
    const float* ln_b   = (const float*)d_in[3];
    const float* temp   = (const float*)d_in[4];
    const float* q_w    = (const float*)d_in[5];
    const float* qdw_w  = (const float*)d_in[6];
    const float* kv_w   = (const float*)d_in[7];
    const float* kvdw_w = (const float*)d_in[8];
    const float* po_w   = (const float*)d_in[9];
    const float* g1_w   = (const float*)d_in[10];
    const float* g1_b   = (const float*)d_in[11];
    const float* g2_w   = (const float*)d_in[12];
    const float* g2_b   = (const float*)d_in[13];
    const float* pin_w  = (const float*)d_in[14];
    const float* dw_w   = (const float*)d_in[15];
    const float* dw1_w  = (const float*)d_in[16];
    const float* dw2_w  = (const float*)d_in[17];
    const float* pout_w = (const float*)d_in[18];
    float* out = (float*)d_out;

    float *p_q1, *p_kv1, *p_x2, *p_t, *p_t2, *p_q, *p_kv, *p_gate;
    cudaGetSymbolAddress((void**)&p_q1,  g_q1);
    cudaGetSymbolAddress((void**)&p_kv1, g_kv1);
    cudaGetSymbolAddress((void**)&p_x2,  g_x2);
    cudaGetSymbolAddress((void**)&p_t,   g_t);
    cudaGetSymbolAddress((void**)&p_t2,  g_t2);
    cudaGetSymbolAddress((void**)&p_q,   g_q);
    cudaGetSymbolAddress((void**)&p_kv,  g_kv);
    cudaGetSymbolAddress((void**)&p_gate,g_gate);

    bf16 *xnh,*xnl,*ynh,*ynl,*zh,*zl,*avh,*avl,*uh,*ul;
    cudaGetSymbolAddress((void**)&xnh, g_xnh); cudaGetSymbolAddress((void**)&xnl, g_xnl);
    cudaGetSymbolAddress((void**)&ynh, g_ynh); cudaGetSymbolAddress((void**)&ynl, g_ynl);
    cudaGetSymbolAddress((void**)&zh,  g_zh);  cudaGetSymbolAddress((void**)&zl,  g_zl);
    cudaGetSymbolAddress((void**)&avh, g_avh); cudaGetSymbolAddress((void**)&avl, g_avl);
    cudaGetSymbolAddress((void**)&uh,  g_uh);  cudaGetSymbolAddress((void**)&ul,  g_ul);
    bf16 *wqh,*wql,*wkvh,*wkvl,*wpoh,*wpol,*wg1h,*wg1l,*wpih,*wpil,*wpth,*wptl;
    cudaGetSymbolAddress((void**)&wqh,  g_wqh);  cudaGetSymbolAddress((void**)&wql,  g_wql);
    cudaGetSymbolAddress((void**)&wkvh, g_wkvh); cudaGetSymbolAddress((void**)&wkvl, g_wkvl);
    cudaGetSymbolAddress((void**)&wpoh, g_wpoh); cudaGetSymbolAddress((void**)&wpol, g_wpol);
    cudaGetSymbolAddress((void**)&wg1h, g_wg1h); cudaGetSymbolAddress((void**)&wg1l, g_wg1l);
    cudaGetSymbolAddress((void**)&wpih, g_wpih); cudaGetSymbolAddress((void**)&wpil, g_wpil);
    cudaGetSymbolAddress((void**)&wpth, g_wpth); cudaGetSymbolAddress((void**)&wptl, g_wptl);

    dim3 lnGrid(NP/256, BB);

    init_kernel<<<1,1>>>();

    convert_w<<<(128*128+255)/256, 256>>>(q_w,    wqh,  wql,  128, 128, 128);
    convert_w<<<(256*128+255)/256, 256>>>(kv_w,   wkvh, wkvl, 256, 128, 128);
    convert_w<<<(128*128+255)/256, 256>>>(po_w,   wpoh, wpol, 128, 128, 128);
    convert_w<<<(64*128 +255)/256, 256>>>(g1_w,   wg1h, wg1l, 64,  128, 128);
    convert_w<<<(680*128+255)/256, 256>>>(pin_w,  wpih, wpil, 680, 128, 128);
    convert_w<<<(128*384+255)/256, 256>>>(pout_w, wpth, wptl, 128, 340, 384);

    ln_kernel<<<lnGrid, 256>>>(x, xnh, xnl, ln_w, ln_b);
    ln_kernel<<<lnGrid, 256>>>(y, ynh, ynl, ln_w, ln_b);

    // q / kv / gate projections (HMMA)
    gemm_wmma<<<dim3(128, 1, BB), 256>>>(wqh,  wql,  128, xnh, xnl, 128, p_q1,  128, 128, (const float*)0, 0, (const float*)0);
    gemm_wmma<<<dim3(128, 2, BB), 256>>>(wkvh, wkvl, 128, ynh, ynl, 128, p_kv1, 256, 256, (const float*)0, 0, (const float*)0);
    gemm_wmma<<<dim3(128, 1, BB), 256>>>(wg1h, wg1l, 128, xnh, xnl, 128, p_gate, 64, 128, g1_b,            1, (const float*)0);

    dwconv3<<<dim3(WW/32, HH/8, BB*CDIM),   256>>>(p_q1,  CDIM,   0, qdw_w,  p_q,  CDIM,   CDIM);
    dwconv3<<<dim3(WW/32, HH/8, BB*2*CDIM), 256>>>(p_kv1, 2*CDIM, 0, kvdw_w, p_kv, 2*CDIM, 2*CDIM);

    gate2_kernel<<<dim3(NP/256, BB), 256>>>(g2_w, g2_b);
    dk_kernel<<<1,1>>>();

    norm_kernel<<<2*BB*CDIM, 256>>>();
    attn_partial<<<dim3(NSPLIT, BB*NHEADS), 256>>>();
    attn_reduce<<<BB*NHEADS, 256>>>(temp);
    masksoftmax<<<2, 256>>>();
    av_kernel<<<dim3(NP/256, BB*NHEADS), 256>>>();

    // project_out + residual
    gemm_wmma<<<dim3(128, 1, BB), 256>>>(wpoh, wpol, 128, avh, avl, 128, p_x2, 128, 128, (const float*)0, 2, x);

    // IEL
    ln_kernel<<<lnGrid, 256>>>(p_x2, zh, zl, ln_w, ln_b);
    gemm_wmma<<<dim3(128, 6, BB), 256>>>(wpih, wpil, 128, zh, zl, 128, p_t, 680, TPAD, (const float*)0, 0, (const float*)0);
    dwconv3<<<dim3(WW/32, HH/8, BB*HID2), 256>>>(p_t, TPAD, 0, dw_w, p_t2, HID2, HID2);
    dw12_fused<<<dim3(WW/32, HH/8, BB*HID), 256>>>(p_t2, dw1_w, dw2_w);
    // pout + residual -> d_out
    gemm_wmma<<<dim3(128, 1, BB), 256>>>(wpth, wptl, 384, uh, ul, 340, out, 128, 128, (const float*)0, 2, p_x2);
}

// round 9
// speedup vs baseline: 1.2404x; 1.0585x over previous
#include <cuda_runtime.h>
#include <cuda_bf16.h>
#include <mma.h>
#include <math.h>

using namespace nvcuda;

#define BB 4
#define CDIM 128
#define HH 128
#define WW 128
#define NP (HH*WW)          // 16384
#define NHEADS 8
#define CH 16
#define HID 340
#define HID2 680
#define TPAD 688            // padded row stride for pin output
#define NSPLIT 32

typedef __nv_bfloat16 bf16;
typedef unsigned int u32;

// ---------------- scratch (device globals; no allocation allowed) ----------------
__device__ __align__(256) bf16 g_xnh[BB*CDIM*NP], g_xnl[BB*CDIM*NP];
__device__ __align__(256) bf16 g_ynh[BB*CDIM*NP], g_ynl[BB*CDIM*NP];
__device__ __align__(256) bf16 g_zh [BB*CDIM*NP], g_zl [BB*CDIM*NP];
__device__ __align__(256) bf16 g_avh[BB*CDIM*NP], g_avl[BB*CDIM*NP];
__device__ __align__(256) bf16 g_uh [BB*HID*NP],  g_ul [BB*HID*NP];
// bf16 hi/lo weights, K-padded row-major [Cout, Kw]
__device__ __align__(256) bf16 g_wqh [128*128],  g_wql [128*128];
__device__ __align__(256) bf16 g_wkvh[256*128],  g_wkvl[256*128];
__device__ __align__(256) bf16 g_wpoh[128*128],  g_wpol[128*128];
__device__ __align__(256) bf16 g_wg1h[64*128],   g_wg1l[64*128];
__device__ __align__(256) bf16 g_wpih[680*128],  g_wpil[680*128];
__device__ __align__(256) bf16 g_wpth[128*384],  g_wptl[128*384];
// fp32 scratch
__device__ float g_q1 [BB*CDIM*NP];
__device__ float g_q  [BB*CDIM*NP];
__device__ float g_kv1[BB*2*CDIM*NP];
__device__ float g_kv [BB*2*CDIM*NP];
__device__ float g_gate[BB*128*NP];          // padded 64 -> 128 rows per batch
__device__ float g_qknorm[2*BB*CDIM];
__device__ float g_attnp[NSPLIT*BB*NHEADS*CH*CH];
__device__ float g_attn [BB*NHEADS*CH*CH];
__device__ float g_x2 [BB*CDIM*NP];
__device__ float g_t  [BB*TPAD*NP];          // padded 680 -> 688 rows per batch
__device__ float g_gsum;
__device__ int   g_dk;

// ---------------- helpers ----------------
__device__ __forceinline__ void f32split(float v, bf16& h, bf16& l) {
    h = __float2bfloat16(v);
    l = __float2bfloat16(v - __bfloat162float(h));
}

__global__ void init_kernel() { g_gsum = 0.f; }

// ---------------- one-shot weight conversion (single launch) ----------------
#define NW_Q   (128*128)
#define NW_KV  (256*128)
#define NW_PO  (128*128)
#define NW_G1  (64*128)
#define NW_PI  (680*128)
#define NW_PT  (128*384)
#define NW_TOT (NW_Q+NW_KV+NW_PO+NW_G1+NW_PI+NW_PT)

__global__ void convert_all(const float* __restrict__ q_w, const float* __restrict__ kv_w,
                            const float* __restrict__ po_w, const float* __restrict__ g1_w,
                            const float* __restrict__ pin_w, const float* __restrict__ pout_w)
{
    int idx = blockIdx.x*256 + threadIdx.x;
    if (idx >= NW_TOT) return;
    const float* W; bf16 *hi, *lo; int Cin, Kw, loc;
    if (idx < NW_Q)                     { loc = idx;                      W = q_w;    hi = g_wqh;  lo = g_wql;  Cin = 128; Kw = 128; }
    else if (idx < NW_Q+NW_KV)          { loc = idx-NW_Q;                 W = kv_w;   hi = g_wkvh; lo = g_wkvl; Cin = 128; Kw = 128; }
    else if (idx < NW_Q+NW_KV+NW_PO)    { loc = idx-NW_Q-NW_KV;           W = po_w;   hi = g_wpoh; lo = g_wpol; Cin = 128; Kw = 128; }
    else if (idx < NW_Q+NW_KV+NW_PO+NW_G1) { loc = idx-NW_Q-NW_KV-NW_PO;  W = g1_w;   hi = g_wg1h; lo = g_wg1l; Cin = 128; Kw = 128; }
    else if (idx < NW_Q+NW_KV+NW_PO+NW_G1+NW_PI) { loc = idx-NW_Q-NW_KV-NW_PO-NW_G1; W = pin_w; hi = g_wpih; lo = g_wpil; Cin = 128; Kw = 128; }
    else                                { loc = idx-NW_Q-NW_KV-NW_PO-NW_G1-NW_PI; W = pout_w; hi = g_wpth; lo = g_wptl; Cin = 340; Kw = 384; }
    int r = loc / Kw, k = loc - r*Kw;
    float v = (k < Cin) ? W[(size_t)r*Cin + k] : 0.f;
    bf16 h, l; f32split(v, h, l);
    hi[loc] = h; lo[loc] = l;
}

// ---------------- LayerNorm (channel axis) -> bf16 hi/lo ----------------
__global__ void __launch_bounds__(256) ln_kernel(const float* __restrict__ In,
                                                 bf16* __restrict__ Oh, bf16* __restrict__ Ol,
                                                 const float* __restrict__ w,
                                                 const float* __restrict__ bta)
{
    int b = blockIdx.y;
    int pos = blockIdx.x*256 + threadIdx.x;
    const float* p = In + (size_t)b*CDIM*NP + pos;
    float s = 0.f, s2 = 0.f;
    #pragma unroll 8
    for (int c = 0; c < CDIM; c++) { float v = p[(size_t)c*NP]; s += v; s2 = fmaf(v, v, s2); }
    float mean = s * (1.f/CDIM);
    float var  = s2 * (1.f/CDIM) - mean*mean;
    float inv  = rsqrtf(var + 1e-6f);
    #pragma unroll 8
    for (int c = 0; c < CDIM; c++) {
        float v = p[(size_t)c*NP];
        float o = w[c]*((v-mean)*inv) + bta[c];
        bf16 h, l; f32split(o, h, l);
        Oh[((size_t)b*CDIM+c)*NP + pos] = h;
        Ol[((size_t)b*CDIM+c)*NP + pos] = l;
    }
}

// ---------------- wmma split-bf16 GEMM ----------------
#define ALD 48
#define BLD 136

__global__ void __launch_bounds__(256, 1)
gemm_wmma(const bf16* __restrict__ Whi, const bf16* __restrict__ Wlo, int Kw,
          const bf16* __restrict__ Ihi, const bf16* __restrict__ Ilo, int Cin,
          float* __restrict__ Out, int CoutW, int CoutPad,
          const float* __restrict__ bias, int mode, const float* __restrict__ resid)
{
    __shared__ __align__(16) bf16 sAh[128*ALD], sAl[128*ALD];
    __shared__ __align__(16) bf16 sBh[32*BLD],  sBl[32*BLD];

    const int tid = threadIdx.x;
    const int warp = tid >> 5, lane = tid & 31;
    const int wr = warp >> 1, wc = warp & 1;
    const int bb = blockIdx.z;
    const int n0 = blockIdx.x * 128;
    const int m0 = blockIdx.y * 128;

    const bf16* inh = Ihi + (size_t)bb*Cin*NP;
    const bf16* inl = Ilo + (size_t)bb*Cin*NP;

    const int a_row0 = (tid*2) >> 2,   a_c0 = ((tid*2) & 3) * 8;
    const int a_row1 = (tid*2+1) >> 2, a_c1 = ((tid*2+1) & 3) * 8;
    const int b_row0 = (tid*2) >> 4,   b_c0 = ((tid*2) & 15) * 8;
    const int b_row1 = (tid*2+1) >> 4, b_c1 = ((tid*2+1) & 15) * 8;

    uint4 pa_h[2], pa_l[2], pb_h[2], pb_l[2];
    const uint4 z4 = make_uint4(0,0,0,0);

    auto ldg = [&](int kc0) {
        int rg0 = m0 + a_row0, rg1 = m0 + a_row1;
        pa_h[0] = (rg0 < CoutW) ? *(const uint4*)(Whi + (size_t)rg0*Kw + kc0 + a_c0) : z4;
        pa_l[0] = (rg0 < CoutW) ? *(const uint4*)(Wlo + (size_t)rg0*Kw + kc0 + a_c0) : z4;
        pa_h[1] = (rg1 < CoutW) ? *(const uint4*)(Whi + (size_t)rg1*Kw + kc0 + a_c1) : z4;
        pa_l[1] = (rg1 < CoutW) ? *(const uint4*)(Wlo + (size_t)rg1*Kw + kc0 + a_c1) : z4;
        int k0 = kc0 + b_row0, k1 = kc0 + b_row1;
        pb_h[0] = (k0 < Cin) ? *(const uint4*)(inh + (size_t)k0*NP + n0 + b_c0) : z4;
        pb_l[0] = (k0 < Cin) ? *(const uint4*)(inl + (size_t)k0*NP + n0 + b_c0) : z4;
        pb_h[1] = (k1 < Cin) ? *(const uint4*)(inh + (size_t)k1*NP + n0 + b_c1) : z4;
        pb_l[1] = (k1 < Cin) ? *(const uint4*)(inl + (size_t)k1*NP + n0 + b_c1) : z4;
    };
    auto sts = [&]() {
        *(uint4*)&sAh[a_row0*ALD + a_c0] = pa_h[0];
        *(uint4*)&sAl[a_row0*ALD + a_c0] = pa_l[0];
        *(uint4*)&sAh[a_row1*ALD + a_c1] = pa_h[1];
        *(uint4*)&sAl[a_row1*ALD + a_c1] = pa_l[1];
        *(uint4*)&sBh[b_row0*BLD + b_c0] = pb_h[0];
        *(uint4*)&sBl[b_row0*BLD + b_c0] = pb_l[0];
        *(uint4*)&sBh[b_row1*BLD + b_c1] = pb_h[1];
        *(uint4*)&sBl[b_row1*BLD + b_c1] = pb_l[1];
    };

    wmma::fragment<wmma::accumulator, 16,16,16, float> acc[2][4];
    #pragma unroll
    for (int mt = 0; mt < 2; mt++)
        #pragma unroll
        for (int nt = 0; nt < 4; nt++) wmma::fill_fragment(acc[mt][nt], 0.f);

    int nchunks = (Cin + 31) >> 5;
    ldg(0);
    sts();

    for (int chn = 0; chn < nchunks; chn++) {
        __syncthreads();
        bool nxt = (chn + 1) < nchunks;
        if (nxt) ldg((chn+1) << 5);

        wmma::fragment<wmma::matrix_a, 16,16,16, bf16, wmma::row_major> fah[2], fal[2];
        wmma::fragment<wmma::matrix_b, 16,16,16, bf16, wmma::row_major> fbh[4], fbl[4];
        #pragma unroll
        for (int ks = 0; ks < 2; ks++) {
            int k16 = ks * 16;
            #pragma unroll
            for (int mt = 0; mt < 2; mt++) {
                wmma::load_matrix_sync(fah[mt], &sAh[(wr*32 + mt*16)*ALD + k16], ALD);
                wmma::load_matrix_sync(fal[mt], &sAl[(wr*32 + mt*16)*ALD + k16], ALD);
            }
            #pragma unroll
            for (int nt = 0; nt < 4; nt++) {
                wmma::load_matrix_sync(fbh[nt], &sBh[k16*BLD + wc*64 + nt*16], BLD);
                wmma::load_matrix_sync(fbl[nt], &sBl[k16*BLD + wc*64 + nt*16], BLD);
            }
            #pragma unroll
            for (int mt = 0; mt < 2; mt++)
                #pragma unroll
                for (int nt = 0; nt < 4; nt++) {
                    wmma::mma_sync(acc[mt][nt], fah[mt], fbh[nt], acc[mt][nt]);
                    wmma::mma_sync(acc[mt][nt], fah[mt], fbl[nt], acc[mt][nt]);
                    wmma::mma_sync(acc[mt][nt], fal[mt], fbh[nt], acc[mt][nt]);
                }
        }
        __syncthreads();
        if (nxt) sts();
    }

    __syncthreads();
    float* stage = reinterpret_cast<float*>(sAh) + warp * 256;
    const int erow = lane >> 1, ec0 = (lane & 1) * 8;
    #pragma unroll
    for (int mt = 0; mt < 2; mt++) {
        #pragma unroll
        for (int nt = 0; nt < 4; nt++) {
            wmma::store_matrix_sync(stage, acc[mt][nt], 16, wmma::mem_row_major);
            __syncwarp();
            int m = m0 + wr*32 + mt*16 + erow;
            int n = n0 + wc*64 + nt*16 + ec0;
            if (m < CoutPad) {
                float v[8];
                #pragma unroll
                for (int j = 0; j < 8; j++) v[j] = stage[erow*16 + ec0 + j];
                if (mode == 1) {
                    float bv = (m < CoutW) ? bias[m] : 0.f;
                    #pragma unroll
                    for (int j = 0; j < 8; j++) v[j] = fmaxf(v[j] + bv, 0.f);
                } else if (mode == 2) {
                    const float* rp = resid + ((size_t)bb*CoutPad + m)*NP + n;
                    float4 r0 = *(const float4*)rp;
                    float4 r1 = *(const float4*)(rp + 4);
                    v[0]+=r0.x; v[1]+=r0.y; v[2]+=r0.z; v[3]+=r0.w;
                    v[4]+=r1.x; v[5]+=r1.y; v[6]+=r1.z; v[7]+=r1.w;
                }
                float* op = Out + ((size_t)bb*CoutPad + m)*NP + n;
                *(float4*)op       = make_float4(v[0],v[1],v[2],v[3]);
                *(float4*)(op + 4) = make_float4(v[4],v[5],v[6],v[7]);
            }
            __syncwarp();
        }
    }
}

// ---------------- depthwise 3x3 conv, pad=1 (fp32) ----------------
__global__ void __launch_bounds__(256) dwconv3(const float* __restrict__ In, int inCtot, int inCbase,
                                               const float* __restrict__ Wd,
                                               float* __restrict__ Out, int outCtot,
                                               int C)
{
    int bc = blockIdx.z;
    int b = bc / C, c = bc % C;
    const float* plane  = In  + ((size_t)b*inCtot + inCbase + c)*NP;
    float*       oplane = Out + ((size_t)b*outCtot + c)*NP;

    __shared__ float t[10][34];
    int tid = threadIdx.x;
    int x0 = blockIdx.x*32, y0 = blockIdx.y*8;
    for (int i = tid; i < 340; i += 256) {
        int sy = i / 34, sx = i % 34;
        int gy = y0 + sy - 1, gx = x0 + sx - 1;
        t[sy][sx] = (gy >= 0 && gy < HH && gx >= 0 && gx < WW) ? plane[gy*WW + gx] : 0.f;
    }
    __syncthreads();
    int tx = tid & 31, ty = tid >> 5;
    const float* w = Wd + (size_t)c*9;
    float s = 0.f;
    #pragma unroll
    for (int ky = 0; ky < 3; ky++)
        #pragma unroll
        for (int kx = 0; kx < 3; kx++)
            s = fmaf(w[ky*3+kx], t[ty+ky][tx+kx], s);
    oplane[(y0+ty)*WW + x0 + tx] = s;
}

// ---------------- fused IEL tail: dw(t) -> mid (smem) -> dw1/dw2 + tanh + gate -> u hi/lo ----------------
__global__ void __launch_bounds__(256) dw_iel_fused(const float* __restrict__ T,
                                                    const float* __restrict__ Wdw,
                                                    const float* __restrict__ W1,
                                                    const float* __restrict__ W2)
{
    int bc = blockIdx.z;
    int b = bc / HID, c = bc % HID;
    const float* p1 = T + ((size_t)b*TPAD + c)*NP;
    const float* p2 = T + ((size_t)b*TPAD + HID + c)*NP;
    size_t uoff = ((size_t)b*HID + c)*NP;

    __shared__ float in1[12][36], in2[12][36];
    __shared__ float m1[10][34],  m2[10][34];

    int tid = threadIdx.x;
    int x0 = blockIdx.x*32, y0 = blockIdx.y*8;

    for (int i = tid; i < 432; i += 256) {
        int sy = i / 36, sx = i % 36;
        int gy = y0 + sy - 2, gx = x0 + sx - 2;
        bool ok = (gy >= 0 && gy < HH && gx >= 0 && gx < WW);
        int gidx = gy*WW + gx;
        in1[sy][sx] = ok ? p1[gidx] : 0.f;
        in2[sy][sx] = ok ? p2[gidx] : 0.f;
    }
    __syncthreads();

    const float* wd1 = Wdw + (size_t)c*9;
    const float* wd2 = Wdw + (size_t)(HID + c)*9;
    for (int i = tid; i < 680; i += 256) {
        int plane = i / 340, cell = i % 340;
        int sy2 = cell / 34, sx2 = cell % 34;
        int gy = y0 + sy2 - 1, gx = x0 + sx2 - 1;
        bool ok = (gy >= 0 && gy < HH && gx >= 0 && gx < WW);
        float s = 0.f;
        if (plane == 0) {
            #pragma unroll
            for (int ky = 0; ky < 3; ky++)
                #pragma unroll
                for (int kx = 0; kx < 3; kx++)
                    s = fmaf(wd1[ky*3+kx], in1[sy2+ky][sx2+kx], s);
            m1[sy2][sx2] = ok ? s : 0.f;
        } else {
            #pragma unroll
            for (int ky = 0; ky < 3; ky++)
                #pragma unroll
                for (int kx = 0; kx < 3; kx++)
                    s = fmaf(wd2[ky*3+kx], in2[sy2+ky][sx2+kx], s);
            m2[sy2][sx2] = ok ? s : 0.f;
        }
    }
    __syncthreads();

    int tx = tid & 31, ty = tid >> 5;
    const float* w1 = W1 + (size_t)c*9;
    const float* w2 = W2 + (size_t)c*9;
    float s1 = 0.f, s2 = 0.f;
    #pragma unroll
    for (int ky = 0; ky < 3; ky++)
        #pragma unroll
        for (int kx = 0; kx < 3; kx++) {
            s1 = fmaf(w1[ky*3+kx], m1[ty+ky][tx+kx], s1);
            s2 = fmaf(w2[ky*3+kx], m2[ty+ky][tx+kx], s2);
        }
    float r1 = tanhf(s1) + m1[ty+1][tx+1];
    float r2 = tanhf(s2) + m2[ty+1][tx+1];
    float u = r1 * r2;
    bf16 h, l; f32split(u, h, l);
    int idx = (y0+ty)*WW + x0 + tx;
    g_uh[uoff + idx] = h;
    g_ul[uoff + idx] = l;
}

// ---------------- gate tail ----------------
__global__ void __launch_bounds__(256) gate2_kernel(const float* __restrict__ w2,
                                                    const float* __restrict__ b2)
{
    int b = blockIdx.y;
    int pos = blockIdx.x*256 + threadIdx.x;
    const float* p = g_gate + (size_t)b*128*NP + pos;
    float s = b2[0];
    #pragma unroll
    for (int c = 0; c < 64; c++) s = fmaf(w2[c], p[(size_t)c*NP], s);
    float sig = 1.f/(1.f + expf(-s));
    __shared__ float red[256];
    red[threadIdx.x] = sig;
    __syncthreads();
    for (int off = 128; off > 0; off >>= 1) {
        if (threadIdx.x < off) red[threadIdx.x] += red[threadIdx.x+off];
        __syncthreads();
    }
    if (threadIdx.x == 0) atomicAdd(&g_gsum, red[0]);
}

__global__ void dk_kernel() {
    float mean = g_gsum / (float)(BB*NP);
    int dk = (int)(16.f * mean);
    if (dk < 1) dk = 1;
    if (dk > CH) dk = CH;
    g_dk = dk;
}

// ---------------- row L2 norms ----------------
__global__ void __launch_bounds__(256) norm_kernel() {
    int r = blockIdx.x;
    const float* p;
    if (r < BB*CDIM) {
        p = g_q + (size_t)r*NP;
    } else {
        int r2 = r - BB*CDIM;
        int b = r2 >> 7, c = r2 & 127;
        p = g_kv + ((size_t)b*2*CDIM + c)*NP;
    }
    float s = 0.f;
    for (int i = threadIdx.x; i < NP; i += 256) { float v = p[i]; s = fmaf(v, v, s); }
    __shared__ float red[256];
    red[threadIdx.x] = s;
    __syncthreads();
    for (int off = 128; off > 0; off >>= 1) {
        if (threadIdx.x < off) red[threadIdx.x] += red[threadIdx.x+off];
        __syncthreads();
    }
    if (threadIdx.x == 0) g_qknorm[r] = sqrtf(red[0]);
}

// ---------------- attention logits ----------------
__global__ void __launch_bounds__(256) attn_partial() {
    int split = blockIdx.x;
    int bh = blockIdx.y;
    int b = bh >> 3, h = bh & 7;
    int tid = threadIdx.x;
    int c = tid >> 4, d = tid & 15;
    __shared__ float qs[128*17];
    __shared__ float ks[128*17];
    float acc = 0.f;
    for (int sub = 0; sub < 4; sub++) {
        int n0 = split*512 + sub*128;
        __syncthreads();
        for (int i = tid; i < 2048; i += 256) {
            int cc = i >> 7, n = i & 127;
            qs[n*17+cc] = g_q [((size_t)b*CDIM   + h*CH + cc)*NP + n0 + n];
            ks[n*17+cc] = g_kv[((size_t)b*2*CDIM + h*CH + cc)*NP + n0 + n];
        }
        __syncthreads();
        #pragma unroll 8
        for (int n = 0; n < 128; n++)
            acc = fmaf(qs[n*17+c], ks[n*17+d], acc);
    }
    g_attnp[((size_t)split*BB*NHEADS + bh)*256 + tid] = acc;
}

__global__ void __launch_bounds__(256) attn_reduce(const float* __restrict__ temp) {
    int bh = blockIdx.x;
    int b = bh >> 3, h = bh & 7;
    int tid = threadIdx.x;
    int c = tid >> 4, d = tid & 15;
    float s = 0.f;
    for (int sp = 0; sp < NSPLIT; sp++)
        s += g_attnp[((size_t)sp*BB*NHEADS + bh)*256 + tid];
    float qn = fmaxf(g_qknorm[b*CDIM + h*CH + c], 1e-12f);
    float kn = fmaxf(g_qknorm[BB*CDIM + b*CDIM + h*CH + d], 1e-12f);
    g_attn[(size_t)bh*256 + tid] = s * temp[h] / (qn * kn);
}

// ---------------- top-k mask + softmax ----------------
__global__ void masksoftmax() {
    int row = blockIdx.x*blockDim.x + threadIdx.x;
    if (row >= BB*NHEADS*CH) return;
    float* base = g_attn + (size_t)row*16;
    float v[16];
    #pragma unroll
    for (int j = 0; j < 16; j++) v[j] = base[j];
    int dk = g_dk;
    bool keep[16];
    float m = -1e30f;
    #pragma unroll
    for (int j = 0; j < 16; j++) {
        int rank = 0;
        #pragma unroll
        for (int i = 0; i < 16; i++)
            rank += (v[i] > v[j]) || (v[i] == v[j] && i < j);
        keep[j] = rank < dk;
        if (keep[j] && v[j] > m) m = v[j];
    }
    float e[16];
    float s = 0.f;
    #pragma unroll
    for (int j = 0; j < 16; j++) { e[j] = keep[j] ? expf(v[j]-m) : 0.f; s += e[j]; }
    float inv = 1.f/s;
    #pragma unroll
    for (int j = 0; j < 16; j++) base[j] = e[j]*inv;
}

// ---------------- out = attn @ v -> av hi/lo ----------------
__global__ void __launch_bounds__(256) av_kernel() {
    int bh = blockIdx.y;
    int b = bh >> 3, h = bh & 7;
    int n = blockIdx.x*256 + threadIdx.x;
    __shared__ float a[256];
    a[threadIdx.x] = g_attn[(size_t)bh*256 + threadIdx.x];
    __syncthreads();
    float acc[16];
    #pragma unroll
    for (int c = 0; c < 16; c++) acc[c] = 0.f;
    #pragma unroll
    for (int d = 0; d < 16; d++) {
        float vv = g_kv[((size_t)b*2*CDIM + CDIM + h*CH + d)*NP + n];
        #pragma unroll
        for (int c = 0; c < 16; c++) acc[c] = fmaf(a[c*16+d], vv, acc[c]);
    }
    #pragma unroll
    for (int c = 0; c < 16; c++) {
        bf16 hh, ll; f32split(acc[c], hh, ll);
        g_avh[((size_t)b*CDIM + h*CH + c)*NP + n] = hh;
        g_avl[((size_t)b*CDIM + h*CH + c)*NP + n] = ll;
    }
}

// ---------------- host launcher ----------------
extern "C" void kernel_launch(void* const* d_in, const int* in_sizes, int n_in,
                              void* d_out, int out_size)
{
    const float* x      = (const float*)d_in[0];
    const float* y      = (const float*)d_in[1];
    const float* ln_w   = (const float*)d_in[2];
    const float* ln_b   = (const float*)d_in[3];
    const float* temp   = (const float*)d_in[4];
    const float* q_w    = (const float*)d_in[5];
    const float* qdw_w  = (const float*)d_in[6];
    const float* kv_w   = (const float*)d_in[7];
    const float* kvdw_w = (const float*)d_in[8];
    const float* po_w   = (const float*)d_in[9];
    const float* g1_w   = (const float*)d_in[10];
    const float* g1_b   = (const float*)d_in[11];
    const float* g2_w   = (const float*)d_in[12];
    const float* g2_b   = (const float*)d_in[13];
    const float* pin_w  = (const float*)d_in[14];
    const float* dw_w   = (const float*)d_in[15];
    const float* dw1_w  = (const float*)d_in[16];
    const float* dw2_w  = (const float*)d_in[17];
    const float* pout_w = (const float*)d_in[18];
    float* out = (float*)d_out;

    float *p_q1, *p_kv1, *p_x2, *p_t, *p_q, *p_kv, *p_gate;
    cudaGetSymbolAddress((void**)&p_q1,  g_q1);
    cudaGetSymbolAddress((void**)&p_kv1, g_kv1);
    cudaGetSymbolAddress((void**)&p_x2,  g_x2);
    cudaGetSymbolAddress((void**)&p_t,   g_t);
    cudaGetSymbolAddress((void**)&p_q,   g_q);
    cudaGetSymbolAddress((void**)&p_kv,  g_kv);
    cudaGetSymbolAddress((void**)&p_gate,g_gate);

    bf16 *xnh,*xnl,*ynh,*ynl,*zh,*zl,*avh,*avl,*uh,*ul;
    cudaGetSymbolAddress((void**)&xnh, g_xnh); cudaGetSymbolAddress((void**)&xnl, g_xnl);
    cudaGetSymbolAddress((void**)&ynh, g_ynh); cudaGetSymbolAddress((void**)&ynl, g_ynl);
    cudaGetSymbolAddress((void**)&zh,  g_zh);  cudaGetSymbolAddress((void**)&zl,  g_zl);
    cudaGetSymbolAddress((void**)&avh, g_avh); cudaGetSymbolAddress((void**)&avl, g_avl);
    cudaGetSymbolAddress((void**)&uh,  g_uh);  cudaGetSymbolAddress((void**)&ul,  g_ul);
    bf16 *wqh,*wql,*wkvh,*wkvl,*wpoh,*wpol,*wg1h,*wg1l,*wpih,*wpil,*wpth,*wptl;
    cudaGetSymbolAddress((void**)&wqh,  g_wqh);  cudaGetSymbolAddress((void**)&wql,  g_wql);
    cudaGetSymbolAddress((void**)&wkvh, g_wkvh); cudaGetSymbolAddress((void**)&wkvl, g_wkvl);
    cudaGetSymbolAddress((void**)&wpoh, g_wpoh); cudaGetSymbolAddress((void**)&wpol, g_wpol);
    cudaGetSymbolAddress((void**)&wg1h, g_wg1h); cudaGetSymbolAddress((void**)&wg1l, g_wg1l);
    cudaGetSymbolAddress((void**)&wpih, g_wpih); cudaGetSymbolAddress((void**)&wpil, g_wpil);
    cudaGetSymbolAddress((void**)&wpth, g_wpth); cudaGetSymbolAddress((void**)&wptl, g_wptl);

    dim3 lnGrid(NP/256, BB);

    // launch order matters for ncu -s 5 -c 1: #6 must be a gemm_wmma
    init_kernel<<<1,1>>>();                                              // 1
    convert_all<<<(NW_TOT+255)/256, 256>>>(q_w, kv_w, po_w, g1_w, pin_w, pout_w);  // 2
    ln_kernel<<<lnGrid, 256>>>(x, xnh, xnl, ln_w, ln_b);                 // 3
    ln_kernel<<<lnGrid, 256>>>(y, ynh, ynl, ln_w, ln_b);                 // 4
    gemm_wmma<<<dim3(128, 1, BB), 256>>>(wqh,  wql,  128, xnh, xnl, 128, p_q1,  128, 128, (const float*)0, 0, (const float*)0);  // 5
    gemm_wmma<<<dim3(128, 2, BB), 256>>>(wkvh, wkvl, 128, ynh, ynl, 128, p_kv1, 256, 256, (const float*)0, 0, (const float*)0);  // 6  <- profiled
    gemm_wmma<<<dim3(128, 1, BB), 256>>>(wg1h, wg1l, 128, xnh, xnl, 128, p_gate, 64, 128, g1_b,            1, (const float*)0);

    dwconv3<<<dim3(WW/32, HH/8, BB*CDIM),   256>>>(p_q1,  CDIM,   0, qdw_w,  p_q,  CDIM,   CDIM);
    dwconv3<<<dim3(WW/32, HH/8, BB*2*CDIM), 256>>>(p_kv1, 2*CDIM, 0, kvdw_w, p_kv, 2*CDIM, 2*CDIM);

    gate2_kernel<<<dim3(NP/256, BB), 256>>>(g2_w, g2_b);
    dk_kernel<<<1,1>>>();

    norm_kernel<<<2*BB*CDIM, 256>>>();
    attn_partial<<<dim3(NSPLIT, BB*NHEADS), 256>>>();
    attn_reduce<<<BB*NHEADS, 256>>>(temp);
    masksoftmax<<<2, 256>>>();
    av_kernel<<<dim3(NP/256, BB*NHEADS), 256>>>();

    // project_out + residual
    gemm_wmma<<<dim3(128, 1, BB), 256>>>(wpoh, wpol, 128, avh, avl, 128, p_x2, 128, 128, (const float*)0, 2, x);

    // IEL
    ln_kernel<<<lnGrid, 256>>>(p_x2, zh, zl, ln_w, ln_b);
    gemm_wmma<<<dim3(128, 6, BB), 256>>>(wpih, wpil, 128, zh, zl, 128, p_t, 680, TPAD, (const float*)0, 0, (const float*)0);
    // fused: t2 = dw(t) in smem; u = (tanh(dw1(x1))+x1)*(tanh(dw2(x2))+x2)
    dw_iel_fused<<<dim3(WW/32, HH/8, BB*HID), 256>>>(p_t, dw_w, dw1_w, dw2_w);
    // pout + residual -> d_out
    gemm_wmma<<<dim3(128, 1, BB), 256>>>(wpth, wptl, 384, uh, ul, 340, out, 128, 128, (const float*)0, 2, p_x2);
}

// round 13
// speedup vs baseline: 1.3358x; 1.0769x over previous
#include <cuda_runtime.h>
#include <cuda_bf16.h>
#include <mma.h>
#include <math.h>

using namespace nvcuda;

#define BB 4
#define CDIM 128
#define HH 128
#define WW 128
#define NP (HH*WW)          // 16384
#define NHEADS 8
#define CH 16
#define HID 340
#define HID2 680
#define TPAD 688
#define NSPLIT 32

typedef __nv_bfloat16 bf16;
typedef unsigned int u32;

// ---------------- scratch ----------------
__device__ __align__(256) bf16 g_xnh[BB*CDIM*NP], g_xnl[BB*CDIM*NP];
__device__ __align__(256) bf16 g_ynh[BB*CDIM*NP], g_ynl[BB*CDIM*NP];
__device__ __align__(256) bf16 g_zh [BB*CDIM*NP], g_zl [BB*CDIM*NP];
__device__ __align__(256) bf16 g_avh[BB*CDIM*NP], g_avl[BB*CDIM*NP];
__device__ __align__(256) bf16 g_uh [BB*HID*NP],  g_ul [BB*HID*NP];
__device__ __align__(256) bf16 g_wqh [128*128],  g_wql [128*128];
__device__ __align__(256) bf16 g_wkvh[256*128],  g_wkvl[256*128];
__device__ __align__(256) bf16 g_wpoh[128*128],  g_wpol[128*128];
__device__ __align__(256) bf16 g_wg1h[64*128],   g_wg1l[64*128];
__device__ __align__(256) bf16 g_wpih[680*128],  g_wpil[680*128];
__device__ __align__(256) bf16 g_wpth[128*384],  g_wptl[128*384];
__device__ float g_q1 [BB*CDIM*NP];
__device__ float g_q  [BB*CDIM*NP];
__device__ float g_kv1[BB*2*CDIM*NP];
__device__ float g_kv [BB*2*CDIM*NP];
__device__ float g_gate[BB*128*NP];
__device__ float g_attnp[NSPLIT*BB*NHEADS*CH*CH];
__device__ float g_normp[NSPLIT*BB*NHEADS*CH*2];
__device__ float g_attn [BB*NHEADS*CH*CH];
__device__ float g_x2 [BB*CDIM*NP];
__device__ float g_t  [BB*TPAD*NP];
__device__ float g_gsum;
__device__ int   g_dk;

__device__ __forceinline__ void f32split(float v, bf16& h, bf16& l) {
    h = __float2bfloat16(v);
    l = __float2bfloat16(v - __bfloat162float(h));
}

__global__ void init_kernel() { g_gsum = 0.f; }

// ---------------- one-shot weight conversion ----------------
#define NW_Q   (128*128)
#define NW_KV  (256*128)
#define NW_PO  (128*128)
#define NW_G1  (64*128)
#define NW_PI  (680*128)
#define NW_PT  (128*384)
#define NW_TOT (NW_Q+NW_KV+NW_PO+NW_G1+NW_PI+NW_PT)

__global__ void convert_all(const float* __restrict__ q_w, const float* __restrict__ kv_w,
                            const float* __restrict__ po_w, const float* __restrict__ g1_w,
                            const float* __restrict__ pin_w, const float* __restrict__ pout_w)
{
    int idx = blockIdx.x*256 + threadIdx.x;
    if (idx >= NW_TOT) return;
    const float* W; bf16 *hi, *lo; int Cin, Kw, loc;
    if (idx < NW_Q)                     { loc = idx;                      W = q_w;    hi = g_wqh;  lo = g_wql;  Cin = 128; Kw = 128; }
    else if (idx < NW_Q+NW_KV)          { loc = idx-NW_Q;                 W = kv_w;   hi = g_wkvh; lo = g_wkvl; Cin = 128; Kw = 128; }
    else if (idx < NW_Q+NW_KV+NW_PO)    { loc = idx-NW_Q-NW_KV;           W = po_w;   hi = g_wpoh; lo = g_wpol; Cin = 128; Kw = 128; }
    else if (idx < NW_Q+NW_KV+NW_PO+NW_G1) { loc = idx-NW_Q-NW_KV-NW_PO;  W = g1_w;   hi = g_wg1h; lo = g_wg1l; Cin = 128; Kw = 128; }
    else if (idx < NW_Q+NW_KV+NW_PO+NW_G1+NW_PI) { loc = idx-NW_Q-NW_KV-NW_PO-NW_G1; W = pin_w; hi = g_wpih; lo = g_wpil; Cin = 128; Kw = 128; }
    else                                { loc = idx-NW_Q-NW_KV-NW_PO-NW_G1-NW_PI; W = pout_w; hi = g_wpth; lo = g_wptl; Cin = 340; Kw = 384; }
    int r = loc / Kw, k = loc - r*Kw;
    float v = (k < Cin) ? W[(size_t)r*Cin + k] : 0.f;
    bf16 h, l; f32split(v, h, l);
    hi[loc] = h; lo[loc] = l;
}

// ---------------- LayerNorm -> bf16 hi/lo ----------------
__global__ void __launch_bounds__(256) ln_kernel(const float* __restrict__ In,
                                                 bf16* __restrict__ Oh, bf16* __restrict__ Ol,
                                                 const float* __restrict__ w,
                                                 const float* __restrict__ bta)
{
    int b = blockIdx.y;
    int pos = blockIdx.x*256 + threadIdx.x;
    const float* p = In + (size_t)b*CDIM*NP + pos;
    float s = 0.f, s2 = 0.f;
    #pragma unroll 8
    for (int c = 0; c < CDIM; c++) { float v = p[(size_t)c*NP]; s += v; s2 = fmaf(v, v, s2); }
    float mean = s * (1.f/CDIM);
    float var  = s2 * (1.f/CDIM) - mean*mean;
    float inv  = rsqrtf(var + 1e-6f);
    #pragma unroll 8
    for (int c = 0; c < CDIM; c++) {
        float v = p[(size_t)c*NP];
        float o = w[c]*((v-mean)*inv) + bta[c];
        bf16 h, l; f32split(o, h, l);
        Oh[((size_t)b*CDIM+c)*NP + pos] = h;
        Ol[((size_t)b*CDIM+c)*NP + pos] = l;
    }
}

// ---------------- wmma split-bf16 GEMM, double-buffered smem ----------------
#define ALD 48
#define BLD 136
#define A_ELEMS (128*ALD)   // 6144 bf16 per stage
#define B_ELEMS (32*BLD)    // 4352 bf16 per stage
#define GSMEM2 (2*(2*A_ELEMS + 2*B_ELEMS)*2)   // 83968 bytes

__global__ void __launch_bounds__(256, 1)
gemm_wmma(const bf16* __restrict__ Whi, const bf16* __restrict__ Wlo, int Kw,
          const bf16* __restrict__ Ihi, const bf16* __restrict__ Ilo, int Cin,
          float* __restrict__ Out, int CoutW, int CoutPad,
          const float* __restrict__ bias, int mode, const float* __restrict__ resid)
{
    extern __shared__ __align__(16) char dsm[];
    bf16* sAh = (bf16*)dsm;                 // [2][A_ELEMS]
    bf16* sAl = sAh + 2*A_ELEMS;
    bf16* sBh = sAl + 2*A_ELEMS;            // [2][B_ELEMS]
    bf16* sBl = sBh + 2*B_ELEMS;

    const int tid = threadIdx.x;
    const int warp = tid >> 5, lane = tid & 31;
    const int wr = warp >> 1, wc = warp & 1;
    const int bb = blockIdx.z;
    const int n0 = blockIdx.x * 128;
    const int m0 = blockIdx.y * 128;

    const bf16* inh = Ihi + (size_t)bb*Cin*NP;
    const bf16* inl = Ilo + (size_t)bb*Cin*NP;

    const int a_row0 = (tid*2) >> 2,   a_c0 = ((tid*2) & 3) * 8;
    const int a_row1 = (tid*2+1) >> 2, a_c1 = ((tid*2+1) & 3) * 8;
    const int b_row0 = (tid*2) >> 4,   b_c0 = ((tid*2) & 15) * 8;
    const int b_row1 = (tid*2+1) >> 4, b_c1 = ((tid*2+1) & 15) * 8;

    uint4 pa_h[2], pa_l[2], pb_h[2], pb_l[2];
    const uint4 z4 = make_uint4(0,0,0,0);

    auto ldg = [&](int kc0) {
        int rg0 = m0 + a_row0, rg1 = m0 + a_row1;
        pa_h[0] = (rg0 < CoutW) ? *(const uint4*)(Whi + (size_t)rg0*Kw + kc0 + a_c0) : z4;
        pa_l[0] = (rg0 < CoutW) ? *(const uint4*)(Wlo + (size_t)rg0*Kw + kc0 + a_c0) : z4;
        pa_h[1] = (rg1 < CoutW) ? *(const uint4*)(Whi + (size_t)rg1*Kw + kc0 + a_c1) : z4;
        pa_l[1] = (rg1 < CoutW) ? *(const uint4*)(Wlo + (size_t)rg1*Kw + kc0 + a_c1) : z4;
        int k0 = kc0 + b_row0, k1 = kc0 + b_row1;
        pb_h[0] = (k0 < Cin) ? *(const uint4*)(inh + (size_t)k0*NP + n0 + b_c0) : z4;
        pb_l[0] = (k0 < Cin) ? *(const uint4*)(inl + (size_t)k0*NP + n0 + b_c0) : z4;
        pb_h[1] = (k1 < Cin) ? *(const uint4*)(inh + (size_t)k1*NP + n0 + b_c1) : z4;
        pb_l[1] = (k1 < Cin) ? *(const uint4*)(inl + (size_t)k1*NP + n0 + b_c1) : z4;
    };
    auto sts = [&](int s) {
        bf16* Ah = sAh + s*A_ELEMS; bf16* Al = sAl + s*A_ELEMS;
        bf16* Bh = sBh + s*B_ELEMS; bf16* Bl = sBl + s*B_ELEMS;
        *(uint4*)&Ah[a_row0*ALD + a_c0] = pa_h[0];
        *(uint4*)&Al[a_row0*ALD + a_c0] = pa_l[0];
        *(uint4*)&Ah[a_row1*ALD + a_c1] = pa_h[1];
        *(uint4*)&Al[a_row1*ALD + a_c1] = pa_l[1];
        *(uint4*)&Bh[b_row0*BLD + b_c0] = pb_h[0];
        *(uint4*)&Bl[b_row0*BLD + b_c0] = pb_l[0];
        *(uint4*)&Bh[b_row1*BLD + b_c1] = pb_h[1];
        *(uint4*)&Bl[b_row1*BLD + b_c1] = pb_l[1];
    };

    wmma::fragment<wmma::accumulator, 16,16,16, float> acc[2][4];
    #pragma unroll
    for (int mt = 0; mt < 2; mt++)
        #pragma unroll
        for (int nt = 0; nt < 4; nt++) wmma::fill_fragment(acc[mt][nt], 0.f);

    int nchunks = (Cin + 31) >> 5;
    ldg(0);
    sts(0);
    __syncthreads();

    int cur = 0;
    for (int chn = 0; chn < nchunks; chn++) {
        bool nxt = (chn + 1) < nchunks;
        if (nxt) ldg((chn+1) << 5);

        const bf16* Ah = sAh + cur*A_ELEMS; const bf16* Al = sAl + cur*A_ELEMS;
        const bf16* Bh = sBh + cur*B_ELEMS; const bf16* Bl = sBl + cur*B_ELEMS;
        wmma::fragment<wmma::matrix_a, 16,16,16, bf16, wmma::row_major> fah[2], fal[2];
        wmma::fragment<wmma::matrix_b, 16,16,16, bf16, wmma::row_major> fbh[4], fbl[4];
        #pragma unroll
        for (int ks = 0; ks < 2; ks++) {
            int k16 = ks * 16;
            #pragma unroll
            for (int mt = 0; mt < 2; mt++) {
                wmma::load_matrix_sync(fah[mt], &Ah[(wr*32 + mt*16)*ALD + k16], ALD);
                wmma::load_matrix_sync(fal[mt], &Al[(wr*32 + mt*16)*ALD + k16], ALD);
            }
            #pragma unroll
            for (int nt = 0; nt < 4; nt++) {
                wmma::load_matrix_sync(fbh[nt], &Bh[k16*BLD + wc*64 + nt*16], BLD);
                wmma::load_matrix_sync(fbl[nt], &Bl[k16*BLD + wc*64 + nt*16], BLD);
            }
            #pragma unroll
            for (int mt = 0; mt < 2; mt++)
                #pragma unroll
                for (int nt = 0; nt < 4; nt++) {
                    wmma::mma_sync(acc[mt][nt], fah[mt], fbh[nt], acc[mt][nt]);
                    wmma::mma_sync(acc[mt][nt], fah[mt], fbl[nt], acc[mt][nt]);
                    wmma::mma_sync(acc[mt][nt], fal[mt], fbh[nt], acc[mt][nt]);
                }
        }
        if (nxt) sts(cur ^ 1);
        __syncthreads();
        cur ^= 1;
    }

    // epilogue (all MMAs done after final barrier; reuse smem as stage)
    float* stage = reinterpret_cast<float*>(dsm) + warp * 256;
    const int erow = lane >> 1, ec0 = (lane & 1) * 8;
    #pragma unroll
    for (int mt = 0; mt < 2; mt++) {
        #pragma unroll
        for (int nt = 0; nt < 4; nt++) {
            wmma::store_matrix_sync(stage, acc[mt][nt], 16, wmma::mem_row_major);
            __syncwarp();
            int m = m0 + wr*32 + mt*16 + erow;
            int n = n0 + wc*64 + nt*16 + ec0;
            if (m < CoutPad) {
                float v[8];
                #pragma unroll
                for (int j = 0; j < 8; j++) v[j] = stage[erow*16 + ec0 + j];
                if (mode == 1) {
                    float bv = (m < CoutW) ? bias[m] : 0.f;
                    #pragma unroll
                    for (int j = 0; j < 8; j++) v[j] = fmaxf(v[j] + bv, 0.f);
                } else if (mode == 2) {
                    const float* rp = resid + ((size_t)bb*CoutPad + m)*NP + n;
                    float4 r0 = *(const float4*)rp;
                    float4 r1 = *(const float4*)(rp + 4);
                    v[0]+=r0.x; v[1]+=r0.y; v[2]+=r0.z; v[3]+=r0.w;
                    v[4]+=r1.x; v[5]+=r1.y; v[6]+=r1.z; v[7]+=r1.w;
                }
                float* op = Out + ((size_t)bb*CoutPad + m)*NP + n;
                *(float4*)op       = make_float4(v[0],v[1],v[2],v[3]);
                *(float4*)(op + 4) = make_float4(v[4],v[5],v[6],v[7]);
            }
            __syncwarp();
        }
    }
}

// ---------------- depthwise 3x3, 32x16 tile, 2 rows/thread ----------------
__global__ void __launch_bounds__(256) dwconv3(const float* __restrict__ In, int inCtot, int inCbase,
                                               const float* __restrict__ Wd,
                                               float* __restrict__ Out, int outCtot,
                                               int C)
{
    int bc = blockIdx.z;
    int b = bc / C, c = bc % C;
    const float* plane  = In  + ((size_t)b*inCtot + inCbase + c)*NP;
    float*       oplane = Out + ((size_t)b*outCtot + c)*NP;

    __shared__ float t[18][34];
    int tid = threadIdx.x;
    int x0 = blockIdx.x*32, y0 = blockIdx.y*16;
    for (int i = tid; i < 612; i += 256) {
        int sy = i / 34, sx = i % 34;
        int gy = y0 + sy - 1, gx = x0 + sx - 1;
        t[sy][sx] = (gy >= 0 && gy < HH && gx >= 0 && gx < WW) ? plane[gy*WW + gx] : 0.f;
    }
    __syncthreads();
    int tx = tid & 31, ty0 = tid >> 5;
    const float* w = Wd + (size_t)c*9;
    #pragma unroll
    for (int rr = 0; rr < 2; rr++) {
        int ty = ty0 + rr*8;
        float s = 0.f;
        #pragma unroll
        for (int ky = 0; ky < 3; ky++)
            #pragma unroll
            for (int kx = 0; kx < 3; kx++)
                s = fmaf(w[ky*3+kx], t[ty+ky][tx+kx], s);
        oplane[(y0+ty)*WW + x0 + tx] = s;
    }
}

// ---------------- fused IEL tail, 32x16 tile ----------------
__global__ void __launch_bounds__(256) dw_iel_fused(const float* __restrict__ T,
                                                    const float* __restrict__ Wdw,
                                                    const float* __restrict__ W1,
                                                    const float* __restrict__ W2)
{
    int bc = blockIdx.z;
    int b = bc / HID, c = bc % HID;
    const float* p1 = T + ((size_t)b*TPAD + c)*NP;
    const float* p2 = T + ((size_t)b*TPAD + HID + c)*NP;
    size_t uoff = ((size_t)b*HID + c)*NP;

    __shared__ float in1[20][36], in2[20][36];
    __shared__ float m1[18][34],  m2[18][34];

    int tid = threadIdx.x;
    int x0 = blockIdx.x*32, y0 = blockIdx.y*16;

    for (int i = tid; i < 720; i += 256) {
        int sy = i / 36, sx = i % 36;
        int gy = y0 + sy - 2, gx = x0 + sx - 2;
        bool ok = (gy >= 0 && gy < HH && gx >= 0 && gx < WW);
        int gidx = gy*WW + gx;
        in1[sy][sx] = ok ? p1[gidx] : 0.f;
        in2[sy][sx] = ok ? p2[gidx] : 0.f;
    }
    __syncthreads();

    const float* wd1 = Wdw + (size_t)c*9;
    const float* wd2 = Wdw + (size_t)(HID + c)*9;
    for (int i = tid; i < 1224; i += 256) {
        int plane = i / 612, cell = i % 612;
        int sy2 = cell / 34, sx2 = cell % 34;
        int gy = y0 + sy2 - 1, gx = x0 + sx2 - 1;
        bool ok = (gy >= 0 && gy < HH && gx >= 0 && gx < WW);
        float s = 0.f;
        if (plane == 0) {
            #pragma unroll
            for (int ky = 0; ky < 3; ky++)
                #pragma unroll
                for (int kx = 0; kx < 3; kx++)
                    s = fmaf(wd1[ky*3+kx], in1[sy2+ky][sx2+kx], s);
            m1[sy2][sx2] = ok ? s : 0.f;
        } else {
            #pragma unroll
            for (int ky = 0; ky < 3; ky++)
                #pragma unroll
                for (int kx = 0; kx < 3; kx++)
                    s = fmaf(wd2[ky*3+kx], in2[sy2+ky][sx2+kx], s);
            m2[sy2][sx2] = ok ? s : 0.f;
        }
    }
    __syncthreads();

    int tx = tid & 31, ty0 = tid >> 5;
    const float* w1 = W1 + (size_t)c*9;
    const float* w2 = W2 + (size_t)c*9;
    #pragma unroll
    for (int rr = 0; rr < 2; rr++) {
        int ty = ty0 + rr*8;
        float s1 = 0.f, s2 = 0.f;
        #pragma unroll
        for (int ky = 0; ky < 3; ky++)
            #pragma unroll
            for (int kx = 0; kx < 3; kx++) {
                s1 = fmaf(w1[ky*3+kx], m1[ty+ky][tx+kx], s1);
                s2 = fmaf(w2[ky*3+kx], m2[ty+ky][tx+kx], s2);
            }
        float r1 = tanhf(s1) + m1[ty+1][tx+1];
        float r2 = tanhf(s2) + m2[ty+1][tx+1];
        float u = r1 * r2;
        bf16 h, l; f32split(u, h, l);
        int idx = (y0+ty)*WW + x0 + tx;
        g_uh[uoff + idx] = h;
        g_ul[uoff + idx] = l;
    }
}

// ---------------- gate tail ----------------
__global__ void __launch_bounds__(256) gate2_kernel(const float* __restrict__ w2,
                                                    const float* __restrict__ b2)
{
    int b = blockIdx.y;
    int pos = blockIdx.x*256 + threadIdx.x;
    const float* p = g_gate + (size_t)b*128*NP + pos;
    float s = b2[0];
    #pragma unroll
    for (int c = 0; c < 64; c++) s = fmaf(w2[c], p[(size_t)c*NP], s);
    float sig = 1.f/(1.f + expf(-s));
    __shared__ float red[256];
    red[threadIdx.x] = sig;
    __syncthreads();
    for (int off = 128; off > 0; off >>= 1) {
        if (threadIdx.x < off) red[threadIdx.x] += red[threadIdx.x+off];
        __syncthreads();
    }
    if (threadIdx.x == 0) atomicAdd(&g_gsum, red[0]);
}

__global__ void dk_kernel() {
    float mean = g_gsum / (float)(BB*NP);
    int dk = (int)(16.f * mean);
    if (dk < 1) dk = 1;
    if (dk > CH) dk = CH;
    g_dk = dk;
}

// ---------------- attention logits + fused norm partials ----------------
__global__ void __launch_bounds__(256) attn_partial() {
    int split = blockIdx.x;
    int bh = blockIdx.y;
    int b = bh >> 3, h = bh & 7;
    int tid = threadIdx.x;
    int c = tid >> 4, d = tid & 15;
    bool diag = (c == d);
    __shared__ float qs[128*17];
    __shared__ float ks[128*17];
    float acc = 0.f, sqq = 0.f, sqk = 0.f;
    for (int sub = 0; sub < 4; sub++) {
        int n0 = split*512 + sub*128;
        __syncthreads();
        for (int i = tid; i < 2048; i += 256) {
            int cc = i >> 7, n = i & 127;
            qs[n*17+cc] = g_q [((size_t)b*CDIM   + h*CH + cc)*NP + n0 + n];
            ks[n*17+cc] = g_kv[((size_t)b*2*CDIM + h*CH + cc)*NP + n0 + n];
        }
        __syncthreads();
        #pragma unroll 8
        for (int n = 0; n < 128; n++) {
            float qv = qs[n*17+c], kv = ks[n*17+d];
            acc = fmaf(qv, kv, acc);
            if (diag) { sqq = fmaf(qv, qv, sqq); sqk = fmaf(kv, kv, sqk); }
        }
    }
    g_attnp[((size_t)split*BB*NHEADS + bh)*256 + tid] = acc;
    if (diag) {
        size_t o = (((size_t)split*BB*NHEADS + bh)*CH + c)*2;
        g_normp[o]   = sqq;
        g_normp[o+1] = sqk;
    }
}

__global__ void __launch_bounds__(256) attn_reduce(const float* __restrict__ temp) {
    int bh = blockIdx.x;
    int h = bh & 7;
    int tid = threadIdx.x;
    int c = tid >> 4, d = tid & 15;
    __shared__ float qn_s[16], kn_s[16];
    if (tid < 32) {
        int cc = tid & 15, which = tid >> 4;
        float s2 = 0.f;
        for (int sp = 0; sp < NSPLIT; sp++)
            s2 += g_normp[(((size_t)sp*BB*NHEADS + bh)*CH + cc)*2 + which];
        float nv = fmaxf(sqrtf(s2), 1e-12f);
        if (which == 0) qn_s[cc] = nv; else kn_s[cc] = nv;
    }
    float s = 0.f;
    for (int sp = 0; sp < NSPLIT; sp++)
        s += g_attnp[((size_t)sp*BB*NHEADS + bh)*256 + tid];
    __syncthreads();
    g_attn[(size_t)bh*256 + tid] = s * temp[h] / (qn_s[c] * kn_s[d]);
}

// ---------------- top-k mask + softmax ----------------
__global__ void masksoftmax() {
    int row = blockIdx.x*blockDim.x + threadIdx.x;
    if (row >= BB*NHEADS*CH) return;
    float* base = g_attn + (size_t)row*16;
    float v[16];
    #pragma unroll
    for (int j = 0; j < 16; j++) v[j] = base[j];
    int dk = g_dk;
    bool keep[16];
    float m = -1e30f;
    #pragma unroll
    for (int j = 0; j < 16; j++) {
        int rank = 0;
        #pragma unroll
        for (int i = 0; i < 16; i++)
            rank += (v[i] > v[j]) || (v[i] == v[j] && i < j);
        keep[j] = rank < dk;
        if (keep[j] && v[j] > m) m = v[j];
    }
    float e[16];
    float s = 0.f;
    #pragma unroll
    for (int j = 0; j < 16; j++) { e[j] = keep[j] ? expf(v[j]-m) : 0.f; s += e[j]; }
    float inv = 1.f/s;
    #pragma unroll
    for (int j = 0; j < 16; j++) base[j] = e[j]*inv;
}

// ---------------- out = attn @ v -> av hi/lo ----------------
__global__ void __launch_bounds__(256) av_kernel() {
    int bh = blockIdx.y;
    int b = bh >> 3, h = bh & 7;
    int n = blockIdx.x*256 + threadIdx.x;
    __shared__ float a[256];
    a[threadIdx.x] = g_attn[(size_t)bh*256 + threadIdx.x];
    __syncthreads();
    float acc[16];
    #pragma unroll
    for (int c = 0; c < 16; c++) acc[c] = 0.f;
    #pragma unroll
    for (int d = 0; d < 16; d++) {
        float vv = g_kv[((size_t)b*2*CDIM + CDIM + h*CH + d)*NP + n];
        #pragma unroll
        for (int c = 0; c < 16; c++) acc[c] = fmaf(a[c*16+d], vv, acc[c]);
    }
    #pragma unroll
    for (int c = 0; c < 16; c++) {
        bf16 hh, ll; f32split(acc[c], hh, ll);
        g_avh[((size_t)b*CDIM + h*CH + c)*NP + n] = hh;
        g_avl[((size_t)b*CDIM + h*CH + c)*NP + n] = ll;
    }
}

// ---------------- host launcher ----------------
extern "C" void kernel_launch(void* const* d_in, const int* in_sizes, int n_in,
                              void* d_out, int out_size)
{
    const float* x      = (const float*)d_in[0];
    const float* y      = (const float*)d_in[1];
    const float* ln_w   = (const float*)d_in[2];
    const float* ln_b   = (const float*)d_in[3];
    const float* temp   = (const float*)d_in[4];
    const float* q_w    = (const float*)d_in[5];
    const float* qdw_w  = (const float*)d_in[6];
    const float* kv_w   = (const float*)d_in[7];
    const float* kvdw_w = (const float*)d_in[8];
    const float* po_w   = (const float*)d_in[9];
    const float* g1_w   = (const float*)d_in[10];
    const float* g1_b   = (const float*)d_in[11];
    const float* g2_w   = (const float*)d_in[12];
    const float* g2_b   = (const float*)d_in[13];
    const float* pin_w  = (const float*)d_in[14];
    const float* dw_w   = (const float*)d_in[15];
    const float* dw1_w  = (const float*)d_in[16];
    const float* dw2_w  = (const float*)d_in[17];
    const float* pout_w = (const float*)d_in[18];
    float* out = (float*)d_out;

    cudaFuncSetAttribute(gemm_wmma, cudaFuncAttributeMaxDynamicSharedMemorySize, GSMEM2);

    float *p_q1, *p_kv1, *p_x2, *p_t, *p_q, *p_kv, *p_gate;
    cudaGetSymbolAddress((void**)&p_q1,  g_q1);
    cudaGetSymbolAddress((void**)&p_kv1, g_kv1);
    cudaGetSymbolAddress((void**)&p_x2,  g_x2);
    cudaGetSymbolAddress((void**)&p_t,   g_t);
    cudaGetSymbolAddress((void**)&p_q,   g_q);
    cudaGetSymbolAddress((void**)&p_kv,  g_kv);
    cudaGetSymbolAddress((void**)&p_gate,g_gate);

    bf16 *xnh,*xnl,*ynh,*ynl,*zh,*zl,*avh,*avl,*uh,*ul;
    cudaGetSymbolAddress((void**)&xnh, g_xnh); cudaGetSymbolAddress((void**)&xnl, g_xnl);
    cudaGetSymbolAddress((void**)&ynh, g_ynh); cudaGetSymbolAddress((void**)&ynl, g_ynl);
    cudaGetSymbolAddress((void**)&zh,  g_zh);  cudaGetSymbolAddress((void**)&zl,  g_zl);
    cudaGetSymbolAddress((void**)&avh, g_avh); cudaGetSymbolAddress((void**)&avl, g_avl);
    cudaGetSymbolAddress((void**)&uh,  g_uh);  cudaGetSymbolAddress((void**)&ul,  g_ul);
    bf16 *wqh,*wql,*wkvh,*wkvl,*wpoh,*wpol,*wg1h,*wg1l,*wpih,*wpil,*wpth,*wptl;
    cudaGetSymbolAddress((void**)&wqh,  g_wqh);  cudaGetSymbolAddress((void**)&wql,  g_wql);
    cudaGetSymbolAddress((void**)&wkvh, g_wkvh); cudaGetSymbolAddress((void**)&wkvl, g_wkvl);
    cudaGetSymbolAddress((void**)&wpoh, g_wpoh); cudaGetSymbolAddress((void**)&wpol, g_wpol);
    cudaGetSymbolAddress((void**)&wg1h, g_wg1h); cudaGetSymbolAddress((void**)&wg1l, g_wg1l);
    cudaGetSymbolAddress((void**)&wpih, g_wpih); cudaGetSymbolAddress((void**)&wpil, g_wpil);
    cudaGetSymbolAddress((void**)&wpth, g_wpth); cudaGetSymbolAddress((void**)&wptl, g_wptl);

    dim3 lnGrid(NP/256, BB);

    init_kernel<<<1,1>>>();
    convert_all<<<(NW_TOT+255)/256, 256>>>(q_w, kv_w, po_w, g1_w, pin_w, pout_w);
    ln_kernel<<<lnGrid, 256>>>(x, xnh, xnl, ln_w, ln_b);
    ln_kernel<<<lnGrid, 256>>>(y, ynh, ynl, ln_w, ln_b);
    gemm_wmma<<<dim3(128, 1, BB), 256, GSMEM2>>>(wqh,  wql,  128, xnh, xnl, 128, p_q1,  128, 128, (const float*)0, 0, (const float*)0);
    gemm_wmma<<<dim3(128, 2, BB), 256, GSMEM2>>>(wkvh, wkvl, 128, ynh, ynl, 128, p_kv1, 256, 256, (const float*)0, 0, (const float*)0);
    gemm_wmma<<<dim3(128, 1, BB), 256, GSMEM2>>>(wg1h, wg1l, 128, xnh, xnl, 128, p_gate, 64, 128, g1_b,            1, (const float*)0);

    dwconv3<<<dim3(WW/32, HH/16, BB*CDIM),   256>>>(p_q1,  CDIM,   0, qdw_w,  p_q,  CDIM,   CDIM);
    dwconv3<<<dim3(WW/32, HH/16, BB*2*CDIM), 256>>>(p_kv1, 2*CDIM, 0, kvdw_w, p_kv, 2*CDIM, 2*CDIM);

    gate2_kernel<<<dim3(NP/256, BB), 256>>>(g2_w, g2_b);
    dk_kernel<<<1,1>>>();

    attn_partial<<<dim3(NSPLIT, BB*NHEADS), 256>>>();
    attn_reduce<<<BB*NHEADS, 256>>>(temp);
    masksoftmax<<<2, 256>>>();
    av_kernel<<<dim3(NP/256, BB*NHEADS), 256>>>();

    // project_out + residual
    gemm_wmma<<<dim3(128, 1, BB), 256, GSMEM2>>>(wpoh, wpol, 128, avh, avl, 128, p_x2, 128, 128, (const float*)0, 2, x);

    // IEL
    ln_kernel<<<lnGrid, 256>>>(p_x2, zh, zl, ln_w, ln_b);
    gemm_wmma<<<dim3(128, 6, BB), 256, GSMEM2>>>(wpih, wpil, 128, zh, zl, 128, p_t, 680, TPAD, (const float*)0, 0, (const float*)0);
    dw_iel_fused<<<dim3(WW/32, HH/16, BB*HID), 256>>>(p_t, dw_w, dw1_w, dw2_w);
    // pout + residual -> d_out
    gemm_wmma<<<dim3(128, 1, BB), 256, GSMEM2>>>(wpth, wptl, 384, uh, ul, 340, out, 128, 128, (const float*)0, 2, p_x2);
}